// round 14
// baseline (speedup 1.0000x reference)
#include <cuda_runtime.h>
#include <cuda_bf16.h>
#include <math.h>
#include <stdint.h>

// ---------------- problem constants ----------------
#define CC      256
#define NHEAD   8
#define HDIM    32
#define SSHIFT  4
#define NWIN    2048
#define TTOT    131072
#define SCALE_F 0.1767766952966369f
#define EPS_F   1e-5f

typedef __nv_bfloat16 bf16;
typedef __nv_bfloat162 bf162;

// ---------------- scratch ----------------
__device__ __align__(16) bf16 g_wt[768 * 256 + 3 * 256 * 256]; // bf16 weights

#define WT_QKV  0
#define WT_PROJ (768 * 256)
#define WT_FC1  (WT_PROJ + 256 * 256)
#define WT_FC2  (WT_FC1 + 256 * 256)

// ---------------- helpers ----------------
__device__ __forceinline__ uint32_t smem_u32(const void* p) {
    uint32_t a;
    asm("{ .reg .u64 t; cvta.to.shared.u64 t, %1; cvt.u32.u64 %0, t; }" : "=r"(a) : "l"(p));
    return a;
}
__device__ __forceinline__ void mma_bf16(float c[4],
                                         uint32_t a0, uint32_t a1, uint32_t a2, uint32_t a3,
                                         uint32_t b0, uint32_t b1) {
    asm volatile(
        "mma.sync.aligned.m16n8k16.row.col.f32.bf16.bf16.f32 "
        "{%0,%1,%2,%3}, {%4,%5,%6,%7}, {%8,%9}, {%0,%1,%2,%3};"
        : "+f"(c[0]), "+f"(c[1]), "+f"(c[2]), "+f"(c[3])
        : "r"(a0), "r"(a1), "r"(a2), "r"(a3), "r"(b0), "r"(b1));
}
__device__ __forceinline__ void ldsm_x4(uint32_t& r0, uint32_t& r1, uint32_t& r2, uint32_t& r3,
                                        uint32_t addr) {
    asm volatile("ldmatrix.sync.aligned.m8n8.x4.shared.b16 {%0,%1,%2,%3}, [%4];"
        : "=r"(r0), "=r"(r1), "=r"(r2), "=r"(r3) : "r"(addr));
}
__device__ __forceinline__ void ldsm_x2(uint32_t& r0, uint32_t& r1, uint32_t addr) {
    asm volatile("ldmatrix.sync.aligned.m8n8.x2.shared.b16 {%0,%1}, [%2];"
        : "=r"(r0), "=r"(r1) : "r"(addr));
}
__device__ __forceinline__ uint32_t pack_bf16(float x, float y) {
    bf162 v = __floats2bfloat162_rn(x, y);
    return *(uint32_t*)&v;
}
#define CP16(dst, src) \
    asm volatile("cp.async.cg.shared.global [%0], [%1], 16;" :: "r"(dst), "l"(src) : "memory")
#define CP_COMMIT() asm volatile("cp.async.commit_group;" ::: "memory")
#define CP_WAIT1()  asm volatile("cp.async.wait_group 1;" ::: "memory")
#define CP_WAIT0()  asm volatile("cp.async.wait_group 0;" ::: "memory")

// windowed row -> original token row (reverse shift)
__device__ __forceinline__ long unwin_row(long wr) {
    int batch = (int)(wr >> 14);
    int win   = ((int)wr >> 6) & 255;
    int token = (int)wr & 63;
    int ys = ((win >> 4) << 3) + (token >> 3);
    int xs = ((win & 15) << 3) + (token & 7);
    int y  = (ys + SSHIFT) & 127;
    int xx = (xs + SSHIFT) & 127;
    return (long)batch * 16384 + y * 128 + xx;
}

// ================ smem layout (bytes) ================
// tileA 0..33792 ; head B stages 33792 + 2x26112 (ends 86016)
// block2 B stages: 33792 + 2x36864 (ends 107520, overlays QS..PS after heads)
// QS 86016 KS 91136 VST 96256 PS 100864 LUT 110080 QB/RED 111104
#define M_TILEA 0
#define M_B     33792
#define M_QS    86016
#define M_KS    91136
#define M_VST   96256
#define M_PS    100864
#define M_LUT   110080
#define M_QB    111104
#define M_RED   111104
#define M_SMEM  114176
#define B2_STG  36864          // block2 stage bytes (256 rows x 144B)

__global__ __launch_bounds__(256, 2)
void swin_block(const float* __restrict__ x,
                const float* __restrict__ g1, const float* __restrict__ b1v,
                const bf16* __restrict__ Wt3, const float* __restrict__ qkvb,
                const float* __restrict__ rel_bias,
                const bf16* __restrict__ Wp, const float* __restrict__ pbias,
                const float* __restrict__ g2, const float* __restrict__ b2,
                const bf16* __restrict__ W1, const float* __restrict__ fb1,
                const bf16* __restrict__ W2, const float* __restrict__ fb2,
                float* __restrict__ out)
{
    extern __shared__ char smc[];
    float*    smF = (float*)smc;
    uint32_t* smW = (uint32_t*)smc;
    bf16*     smH = (bf16*)smc;
    uint32_t  sm0 = smem_u32(smc);

    int tid = threadIdx.x, warp = tid >> 5, lane = tid & 31;
    int g = lane >> 2, t = lane & 3;
    int lr  = lane & 7;
    int x4r = lr + ((lane >> 3) & 1) * 8;
    int x4c = ((lane >> 4) & 1) * 4;
    int x2c = ((lane >> 3) & 1) * 4;
    int bx4r = lr + ((lane >> 4) & 1) * 8;
    int bx4c = ((lane >> 3) & 1) * 4;
    long bm = (long)blockIdx.x * 64;

    float* qb  = smF + M_QB / 4;
    float* lut = smF + M_LUT / 4;

    #pragma unroll
    for (int i = 0; i < 3; i++) qb[tid + i * 256] = qkvb[tid + i * 256];

    auto loadB1 = [&](int buf, int h, int kc) {
        uint32_t Bs = sm0 + M_B + buf * 26112;
        const bf16* src = Wt3 + (size_t)h * 96 * 256 + kc * 128;
        #pragma unroll
        for (int i = 0; i < 6; i++) {
            int e = tid + i * 256;
            int row = e >> 4, c8 = (e & 15) * 8;
            CP16(Bs + row * 272 + c8 * 2, src + row * 256 + c8);
        }
    };
    // block2 weight stage: one row per thread, 8 consecutive CP16
    auto loadW64 = [&](int buf, int k0, const bf16* W) {
        uint32_t Bs = sm0 + M_B + buf * B2_STG + tid * 144;
        const bf16* src = W + (size_t)tid * 256 + k0;
        #pragma unroll
        for (int i = 0; i < 8; i++)
            CP16(Bs + i * 16, src + i * 8);
    };

    loadB1(0, 0, 0); CP_COMMIT();
    loadB1(1, 0, 1); CP_COMMIT();

    // ---- LN1 + shifted-window gather into tileA ----
    for (int i = 0; i < 8; i++) {
        int r = warp * 8 + i;
        long srow = unwin_row(bm + r);
        const float4* px = (const float4*)(x + srow * 256);
        float4 v0 = px[lane * 2], v1 = px[lane * 2 + 1];
        float s  = v0.x + v0.y + v0.z + v0.w + v1.x + v1.y + v1.z + v1.w;
        float s2 = v0.x*v0.x + v0.y*v0.y + v0.z*v0.z + v0.w*v0.w
                 + v1.x*v1.x + v1.y*v1.y + v1.z*v1.z + v1.w*v1.w;
        #pragma unroll
        for (int o = 16; o > 0; o >>= 1) {
            s  += __shfl_xor_sync(0xffffffffu, s,  o);
            s2 += __shfl_xor_sync(0xffffffffu, s2, o);
        }
        float mean = s * (1.0f / 256.0f);
        float inv = rsqrtf(s2 * (1.0f / 256.0f) - mean * mean + EPS_F);
        float4 ga = *(const float4*)(g1 + lane * 8);
        float4 gb = *(const float4*)(g1 + lane * 8 + 4);
        float4 ba = *(const float4*)(b1v + lane * 8);
        float4 bb = *(const float4*)(b1v + lane * 8 + 4);
        uint4 o4;
        o4.x = pack_bf16((v0.x - mean) * inv * ga.x + ba.x, (v0.y - mean) * inv * ga.y + ba.y);
        o4.y = pack_bf16((v0.z - mean) * inv * ga.z + ba.z, (v0.w - mean) * inv * ga.w + ba.w);
        o4.z = pack_bf16((v1.x - mean) * inv * gb.x + bb.x, (v1.y - mean) * inv * gb.y + bb.y);
        o4.w = pack_bf16((v1.z - mean) * inv * gb.z + bb.z, (v1.w - mean) * inv * gb.w + bb.w);
        *(uint4*)(smH + r * 264 + lane * 8) = o4;
    }

    int wmq = (warp & 3) * 16;
    int wnq = (warp >> 2) * 48;

    uint32_t oacc[8][4];      // per-head PV output (packed bf16 pairs)

    #pragma unroll 1
    for (int h = 0; h < 8; h++) {
        CP_WAIT1();
        __syncthreads();

        // lut for head h: hoisted so its latency hides under the GEMM
        if (tid < 225) lut[tid] = rel_bias[tid * 8 + h];

        // ---- qkv GEMM for head h: 64x96x256 ----
        float c[6][4];
        #pragma unroll
        for (int ni = 0; ni < 6; ni++)
            #pragma unroll
            for (int r = 0; r < 4; r++) c[ni][r] = 0.f;

        #pragma unroll
        for (int kc = 0; kc < 2; kc++) {
            if (kc == 1) CP_WAIT0();
            uint32_t Bb = sm0 + M_B + kc * 26112;
            #pragma unroll
            for (int ks = 0; ks < 8; ks++) {
                int kw = ks * 8;
                uint32_t a0, a1, a2, a3;
                ldsm_x4(a0, a1, a2, a3,
                        sm0 + ((wmq + x4r) * 132 + kc * 64 + kw + x4c) * 4);
                #pragma unroll
                for (int ni = 0; ni < 6; ni++) {
                    uint32_t b0, b1;
                    ldsm_x2(b0, b1, Bb + ((wnq + ni * 8 + lr) * 68 + kw + x2c) * 4);
                    mma_bf16(c[ni], a0, a1, a2, a3, b0, b1);
                }
            }
        }

        // ---- stage q/k/v (+bias): branch-free per warp half ----
        {
            int lr0 = wmq + g, lr1 = lr0 + 8;
            if (warp < 4) {
                #pragma unroll
                for (int ni = 0; ni < 4; ni++) {
                    int cj = ni * 8 + 2 * t;
                    float bb0 = qb[h * 32 + cj], bb1 = qb[h * 32 + cj + 1];
                    smW[M_QS / 4 + lr0 * 20 + (cj >> 1)] = pack_bf16(c[ni][0] + bb0, c[ni][1] + bb1);
                    smW[M_QS / 4 + lr1 * 20 + (cj >> 1)] = pack_bf16(c[ni][2] + bb0, c[ni][3] + bb1);
                }
                #pragma unroll
                for (int ni = 4; ni < 6; ni++) {
                    int cj = (ni - 4) * 8 + 2 * t;
                    float bb0 = qb[256 + h * 32 + cj], bb1 = qb[256 + h * 32 + cj + 1];
                    smW[M_KS / 4 + lr0 * 20 + (cj >> 1)] = pack_bf16(c[ni][0] + bb0, c[ni][1] + bb1);
                    smW[M_KS / 4 + lr1 * 20 + (cj >> 1)] = pack_bf16(c[ni][2] + bb0, c[ni][3] + bb1);
                }
            } else {
                #pragma unroll
                for (int ni = 0; ni < 2; ni++) {
                    int cj = 16 + ni * 8 + 2 * t;
                    float bb0 = qb[256 + h * 32 + cj], bb1 = qb[256 + h * 32 + cj + 1];
                    smW[M_KS / 4 + lr0 * 20 + (cj >> 1)] = pack_bf16(c[ni][0] + bb0, c[ni][1] + bb1);
                    smW[M_KS / 4 + lr1 * 20 + (cj >> 1)] = pack_bf16(c[ni][2] + bb0, c[ni][3] + bb1);
                }
                bf16* ve = smH + M_VST / 2;
                #pragma unroll
                for (int ni = 2; ni < 6; ni++) {
                    int cj = (ni - 2) * 8 + 2 * t;
                    float bb0 = qb[512 + h * 32 + cj], bb1 = qb[512 + h * 32 + cj + 1];
                    ve[cj * 72 + lr0]       = __float2bfloat16_rn(c[ni][0] + bb0);
                    ve[(cj + 1) * 72 + lr0] = __float2bfloat16_rn(c[ni][1] + bb1);
                    ve[cj * 72 + lr1]       = __float2bfloat16_rn(c[ni][2] + bb0);
                    ve[(cj + 1) * 72 + lr1] = __float2bfloat16_rn(c[ni][3] + bb1);
                }
            }
        }
        __syncthreads();

        if (h < 7) {
            loadB1(0, h + 1, 0); CP_COMMIT();
            loadB1(1, h + 1, 1); CP_COMMIT();
        } else {
            // qkv B stages dead: start proj weights now (hides under softmax+PV)
            loadW64(0, 0, Wp); CP_COMMIT();
        }

        // ---- QK + softmax: warps 0..3 ----
        if (warp < 4) {
            int wm2 = warp * 16;
            float s[8][4];
            #pragma unroll
            for (int ni = 0; ni < 8; ni++)
                #pragma unroll
                for (int r = 0; r < 4; r++) s[ni][r] = 0.f;

            #pragma unroll
            for (int kt = 0; kt < 2; kt++) {
                int kw = kt * 8;
                uint32_t a0, a1, a2, a3;
                ldsm_x4(a0, a1, a2, a3,
                        sm0 + M_QS + ((wm2 + x4r) * 20 + kw + x4c) * 4);
                #pragma unroll
                for (int ni = 0; ni < 8; ni++) {
                    uint32_t b0, b1;
                    ldsm_x2(b0, b1, sm0 + M_KS + ((ni * 8 + lr) * 20 + kw + x2c) * 4);
                    mma_bf16(s[ni], a0, a1, a2, a3, b0, b1);
                }
            }

            int r0 = wm2 + g, r1 = wm2 + g + 8;
            int rh0 = r0 >> 3, rw0 = r0 & 7;
            int rh1 = r1 >> 3, rw1 = r1 & 7;
            float mx0 = -1e30f, mx1 = -1e30f;
            #pragma unroll
            for (int ni = 0; ni < 8; ni++) {
                #pragma unroll
                for (int cc2 = 0; cc2 < 2; cc2++) {
                    int col = ni * 8 + 2 * t + cc2;
                    int mh = col >> 3, mw = col & 7;
                    s[ni][cc2]     = s[ni][cc2]     * SCALE_F + lut[(rh0 - mh + 7) * 15 + (rw0 - mw + 7)];
                    s[ni][2 + cc2] = s[ni][2 + cc2] * SCALE_F + lut[(rh1 - mh + 7) * 15 + (rw1 - mw + 7)];
                    mx0 = fmaxf(mx0, s[ni][cc2]);
                    mx1 = fmaxf(mx1, s[ni][2 + cc2]);
                }
            }
            mx0 = fmaxf(mx0, __shfl_xor_sync(0xffffffffu, mx0, 1));
            mx0 = fmaxf(mx0, __shfl_xor_sync(0xffffffffu, mx0, 2));
            mx1 = fmaxf(mx1, __shfl_xor_sync(0xffffffffu, mx1, 1));
            mx1 = fmaxf(mx1, __shfl_xor_sync(0xffffffffu, mx1, 2));
            float sum0 = 0.f, sum1 = 0.f;
            #pragma unroll
            for (int ni = 0; ni < 8; ni++) {
                s[ni][0] = __expf(s[ni][0] - mx0); sum0 += s[ni][0];
                s[ni][1] = __expf(s[ni][1] - mx0); sum0 += s[ni][1];
                s[ni][2] = __expf(s[ni][2] - mx1); sum1 += s[ni][2];
                s[ni][3] = __expf(s[ni][3] - mx1); sum1 += s[ni][3];
            }
            sum0 += __shfl_xor_sync(0xffffffffu, sum0, 1);
            sum0 += __shfl_xor_sync(0xffffffffu, sum0, 2);
            sum1 += __shfl_xor_sync(0xffffffffu, sum1, 1);
            sum1 += __shfl_xor_sync(0xffffffffu, sum1, 2);
            float inv0 = 1.0f / sum0, inv1 = 1.0f / sum1;
            #pragma unroll
            for (int ni = 0; ni < 8; ni++) {
                smW[M_PS / 4 + r0 * 36 + ni * 4 + t] = pack_bf16(s[ni][0] * inv0, s[ni][1] * inv0);
                smW[M_PS / 4 + r1 * 36 + ni * 4 + t] = pack_bf16(s[ni][2] * inv1, s[ni][3] * inv1);
            }
        }
        __syncthreads();

        // ---- PV: all 8 warps, 16 rows x 16 cols -> oacc ----
        {
            int rowb = (warp & 3) * 16, colb = (warp >> 2) * 16;
            float o[2][4];
            #pragma unroll
            for (int ni = 0; ni < 2; ni++)
                #pragma unroll
                for (int r = 0; r < 4; r++) o[ni][r] = 0.f;
            #pragma unroll
            for (int kt = 0; kt < 4; kt++) {
                int kw = kt * 8;
                uint32_t a0, a1, a2, a3;
                ldsm_x4(a0, a1, a2, a3,
                        sm0 + M_PS + ((rowb + x4r) * 36 + kw + x4c) * 4);
                #pragma unroll
                for (int ni = 0; ni < 2; ni++) {
                    uint32_t b0, b1;
                    ldsm_x2(b0, b1, sm0 + M_VST + ((colb + ni * 8 + lr) * 36 + kw + x2c) * 4);
                    mma_bf16(o[ni], a0, a1, a2, a3, b0, b1);
                }
            }
            #pragma unroll
            for (int ni = 0; ni < 2; ni++) {
                oacc[h][ni * 2]     = pack_bf16(o[ni][0], o[ni][1]);
                oacc[h][ni * 2 + 1] = pack_bf16(o[ni][2], o[ni][3]);
            }
        }
    }

    // ---- dump attn out into tileA (LN1 data dead) ----
    __syncthreads();
    {
        int rowb = (warp & 3) * 16, colb = (warp >> 2) * 16;
        #pragma unroll
        for (int h = 0; h < 8; h++) {
            #pragma unroll
            for (int ni = 0; ni < 2; ni++) {
                int wcol = h * 16 + (colb >> 1) + ni * 4 + t;
                smW[(rowb + g) * 132 + wcol]     = oacc[h][ni * 2];
                smW[(rowb + g + 8) * 132 + wcol] = oacc[h][ni * 2 + 1];
            }
        }
    }
    __syncthreads();
    // QS..PS dead now: load proj stage 1 (hides under nothing but issues early)
    loadW64(1, 64, Wp); CP_COMMIT();

    // ================== block2 phases ==================
    int wm = (warp & 1) * 32, wn = (warp >> 1) * 64, wnid = warp >> 1;
    float* red = smF + M_RED / 4;

    int lr0[2], lr1[2];
    long t0[2], t1[2];
    #pragma unroll
    for (int mi = 0; mi < 2; mi++) {
        lr0[mi] = wm + mi * 16 + g;
        lr1[mi] = lr0[mi] + 8;
        t0[mi] = unwin_row(bm + lr0[mi]);
        t1[mi] = unwin_row(bm + lr1[mi]);
    }

    float c[2][8][4];

    auto compS = [&](int buf, int itk) {
        uint32_t Bb = sm0 + M_B + buf * B2_STG;
        #pragma unroll
        for (int kt = 0; kt < 4; kt++) {
            int kwg = itk * 32 + kt * 8;
            uint32_t a[2][4];
            #pragma unroll
            for (int mi = 0; mi < 2; mi++)
                ldsm_x4(a[mi][0], a[mi][1], a[mi][2], a[mi][3],
                        sm0 + ((wm + mi * 16 + x4r) * 132 + kwg + x4c) * 4);
            #pragma unroll
            for (int np = 0; np < 4; np++) {
                uint32_t b0, b1, b2, b3;
                ldsm_x4(b0, b1, b2, b3,
                        Bb + ((wn + np * 16 + bx4r) * 36 + kt * 8 + bx4c) * 4);
                mma_bf16(c[0][2*np],   a[0][0], a[0][1], a[0][2], a[0][3], b0, b1);
                mma_bf16(c[1][2*np],   a[1][0], a[1][1], a[1][2], a[1][3], b0, b1);
                mma_bf16(c[0][2*np+1], a[0][0], a[0][1], a[0][2], a[0][3], b2, b3);
                mma_bf16(c[1][2*np+1], a[1][0], a[1][1], a[1][2], a[1][3], b2, b3);
            }
        }
    };
    auto zeroC = [&]() {
        #pragma unroll
        for (int mi = 0; mi < 2; mi++)
            #pragma unroll
            for (int ni = 0; ni < 8; ni++)
                #pragma unroll
                for (int r = 0; r < 4; r++) c[mi][ni][r] = 0.f;
    };
    // Phase pipeline: on entry, L0/L1 of THIS phase's W are committed.
    // it2/it3 free their buffers -> prefetch NEXT phase's L0/L1 there.
    auto run_phase = [&](const bf16* W, const bf16* Wnext, bool has_next) {
        zeroC();
        CP_WAIT1();          // this phase's L0 done
        __syncthreads();
        #pragma unroll 1
        for (int it = 0; it < 4; ++it) {
            compS(it & 1, it);
            __syncthreads();                 // all warps done reading buf (it&1)
            if (it < 2) {
                loadW64(it & 1, (it + 2) * 64, W); CP_COMMIT();
                CP_WAIT1();                  // buf ((it+1)&1) data arrived
                __syncthreads();
            } else if (it == 2) {
                if (has_next) { loadW64(0, 0, Wnext); CP_COMMIT(); CP_WAIT1(); }
                else CP_WAIT0();
                __syncthreads();
            } else { // it == 3
                if (has_next) { loadW64(1, 64, Wnext); CP_COMMIT(); }
                // epilogue provides the trailing barrier
            }
        }
    };

    // ---- phase 1: proj (A = attn out in tileA) ----
    run_phase(Wp, W1, true);
    {
        float s0[2] = {0.f, 0.f}, q0[2] = {0.f, 0.f};
        float s1[2] = {0.f, 0.f}, q1[2] = {0.f, 0.f};
        #pragma unroll
        for (int mi = 0; mi < 2; mi++) {
            #pragma unroll
            for (int ni = 0; ni < 8; ni++) {
                int col = wn + ni * 8 + 2 * t;
                float b0 = pbias[col], b1 = pbias[col + 1];
                float2 ra = *(const float2*)(x + t0[mi] * 256 + col);
                float2 rb = *(const float2*)(x + t1[mi] * 256 + col);
                float v0 = c[mi][ni][0] + b0 + ra.x;
                float v1 = c[mi][ni][1] + b1 + ra.y;
                float v2 = c[mi][ni][2] + b0 + rb.x;
                float v3 = c[mi][ni][3] + b1 + rb.y;
                *(float2*)(out + t0[mi] * 256 + col) = make_float2(v0, v1);
                *(float2*)(out + t1[mi] * 256 + col) = make_float2(v2, v3);
                c[mi][ni][0] = v0; c[mi][ni][1] = v1;
                c[mi][ni][2] = v2; c[mi][ni][3] = v3;
                s0[mi] += v0 + v1; q0[mi] += v0 * v0 + v1 * v1;
                s1[mi] += v2 + v3; q1[mi] += v2 * v2 + v3 * v3;
            }
        }
        #pragma unroll
        for (int o = 1; o < 4; o <<= 1) {
            #pragma unroll
            for (int mi = 0; mi < 2; mi++) {
                s0[mi] += __shfl_xor_sync(0xffffffffu, s0[mi], o);
                q0[mi] += __shfl_xor_sync(0xffffffffu, q0[mi], o);
                s1[mi] += __shfl_xor_sync(0xffffffffu, s1[mi], o);
                q1[mi] += __shfl_xor_sync(0xffffffffu, q1[mi], o);
            }
        }
        if (t == 0) {
            #pragma unroll
            for (int mi = 0; mi < 2; mi++) {
                red[lr0[mi] * 8 + wnid * 2]     = s0[mi];
                red[lr0[mi] * 8 + wnid * 2 + 1] = q0[mi];
                red[lr1[mi] * 8 + wnid * 2]     = s1[mi];
                red[lr1[mi] * 8 + wnid * 2 + 1] = q1[mi];
            }
        }
        __syncthreads();
        #pragma unroll
        for (int mi = 0; mi < 2; mi++) {
            float sa = 0.f, qa = 0.f, sb = 0.f, qb2 = 0.f;
            #pragma unroll
            for (int j = 0; j < 4; j++) {
                sa  += red[lr0[mi] * 8 + j * 2];
                qa  += red[lr0[mi] * 8 + j * 2 + 1];
                sb  += red[lr1[mi] * 8 + j * 2];
                qb2 += red[lr1[mi] * 8 + j * 2 + 1];
            }
            float m0 = sa * (1.0f / 256.0f);
            float i0 = rsqrtf(qa * (1.0f / 256.0f) - m0 * m0 + EPS_F);
            float m1 = sb * (1.0f / 256.0f);
            float i1 = rsqrtf(qb2 * (1.0f / 256.0f) - m1 * m1 + EPS_F);
            #pragma unroll
            for (int ni = 0; ni < 8; ni++) {
                int col = wn + ni * 8 + 2 * t;
                float2 gg = *(const float2*)(g2 + col);
                float2 bb = *(const float2*)(b2 + col);
                smW[lr0[mi] * 132 + (col >> 1)] =
                    pack_bf16((c[mi][ni][0] - m0) * i0 * gg.x + bb.x,
                              (c[mi][ni][1] - m0) * i0 * gg.y + bb.y);
                smW[lr1[mi] * 132 + (col >> 1)] =
                    pack_bf16((c[mi][ni][2] - m1) * i1 * gg.x + bb.x,
                              (c[mi][ni][3] - m1) * i1 * gg.y + bb.y);
            }
        }
    }
    __syncthreads();

    // ---- phase 2: fc1 + GELU ----
    run_phase(W1, W2, true);
    #pragma unroll
    for (int mi = 0; mi < 2; mi++) {
        #pragma unroll
        for (int ni = 0; ni < 8; ni++) {
            int col = wn + ni * 8 + 2 * t;
            float b0 = fb1[col], b1 = fb1[col + 1];
            float v0 = c[mi][ni][0] + b0;
            float v1 = c[mi][ni][1] + b1;
            float v2 = c[mi][ni][2] + b0;
            float v3 = c[mi][ni][3] + b1;
            v0 = 0.5f * v0 * (1.0f + erff(v0 * 0.70710678118654752f));
            v1 = 0.5f * v1 * (1.0f + erff(v1 * 0.70710678118654752f));
            v2 = 0.5f * v2 * (1.0f + erff(v2 * 0.70710678118654752f));
            v3 = 0.5f * v3 * (1.0f + erff(v3 * 0.70710678118654752f));
            smW[lr0[mi] * 132 + (col >> 1)] = pack_bf16(v0, v1);
            smW[lr1[mi] * 132 + (col >> 1)] = pack_bf16(v2, v3);
        }
    }
    __syncthreads();

    // ---- phase 3: fc2 + residual (x2 re-read from out) ----
    run_phase(W2, W2, false);
    #pragma unroll
    for (int mi = 0; mi < 2; mi++) {
        #pragma unroll
        for (int ni = 0; ni < 8; ni++) {
            int col = wn + ni * 8 + 2 * t;
            float b0 = fb2[col], b1 = fb2[col + 1];
            float2 ra = *(const float2*)(out + t0[mi] * 256 + col);
            float2 rb = *(const float2*)(out + t1[mi] * 256 + col);
            *(float2*)(out + t0[mi] * 256 + col) =
                make_float2(c[mi][ni][0] + b0 + ra.x, c[mi][ni][1] + b1 + ra.y);
            *(float2*)(out + t1[mi] * 256 + col) =
                make_float2(c[mi][ni][2] + b0 + rb.x, c[mi][ni][3] + b1 + rb.y);
        }
    }
}

// ================ merged weight convert (single launch) ================
__global__ void cvt_all(const float* __restrict__ qkv_w, const float* __restrict__ proj_w,
                        const float* __restrict__ fc1_w, const float* __restrict__ fc2_w,
                        bf16* __restrict__ wt)
{
    __shared__ float tsm[32][33];
    int bx = blockIdx.x;
    int k0 = blockIdx.y * 32;
    int tx = threadIdx.x, ty = threadIdx.y;
    if (bx < 24) {
        int n0 = bx * 32;
        int n = n0 + tx;
        int h = n / 96, j = n % 96;
        int cidx = (j >> 5) * 256 + h * 32 + (j & 31);
        tsm[ty][tx] = qkv_w[(size_t)(k0 + ty) * 768 + cidx];
        __syncthreads();
        wt[WT_QKV + (size_t)(n0 + ty) * 256 + k0 + tx] = __float2bfloat16_rn(tsm[tx][ty]);
    } else {
        int s = (bx - 24) >> 3;
        int n0 = ((bx - 24) & 7) * 32;
        const float* W = (s == 0) ? proj_w : ((s == 1) ? fc1_w : fc2_w);
        size_t base = (s == 0) ? WT_PROJ : ((s == 1) ? WT_FC1 : WT_FC2);
        tsm[ty][tx] = W[(size_t)(k0 + ty) * 256 + n0 + tx];
        __syncthreads();
        wt[base + (size_t)(n0 + ty) * 256 + k0 + tx] = __float2bfloat16_rn(tsm[tx][ty]);
    }
}

// ---------------- launch ----------------
extern "C" void kernel_launch(void* const* d_in, const int* in_sizes, int n_in,
                              void* d_out, int out_size)
{
    const float* x       = (const float*)d_in[0];
    const float* norm1_g = (const float*)d_in[1];
    const float* norm1_b = (const float*)d_in[2];
    const float* qkv_w   = (const float*)d_in[3];
    const float* qkv_b   = (const float*)d_in[4];
    const float* rel_b   = (const float*)d_in[5];
    const float* proj_w  = (const float*)d_in[6];
    const float* proj_b  = (const float*)d_in[7];
    const float* norm2_g = (const float*)d_in[8];
    const float* norm2_b = (const float*)d_in[9];
    const float* fc1_w   = (const float*)d_in[10];
    const float* fc1_b   = (const float*)d_in[11];
    const float* fc2_w   = (const float*)d_in[12];
    const float* fc2_b   = (const float*)d_in[13];
    float* out = (float*)d_out;

    bf16* p_wt;
    cudaGetSymbolAddress((void**)&p_wt, g_wt);

    cudaFuncSetAttribute(swin_block, cudaFuncAttributeMaxDynamicSharedMemorySize, M_SMEM);

    // 0) merged weight convert
    cvt_all<<<dim3(48, 8), dim3(32, 32)>>>(qkv_w, proj_w, fc1_w, fc2_w, p_wt);

    // 1) whole Swin block in one kernel: one window per CTA
    swin_block<<<NWIN, 256, M_SMEM>>>(
        x, norm1_g, norm1_b, p_wt + WT_QKV, qkv_b, rel_b,
        p_wt + WT_PROJ, proj_b, norm2_g, norm2_b,
        p_wt + WT_FC1, fc1_b, p_wt + WT_FC2, fc2_b, out);
}

// round 15
// speedup vs baseline: 1.2169x; 1.2169x over previous
#include <cuda_runtime.h>
#include <cuda_bf16.h>
#include <math.h>
#include <stdint.h>

// ---------------- problem constants ----------------
#define CC      256
#define NHEAD   8
#define HDIM    32
#define SSHIFT  4
#define NWIN    2048
#define TTOT    131072
#define SCALE_F 0.1767766952966369f
#define EPS_F   1e-5f

typedef __nv_bfloat16 bf16;
typedef __nv_bfloat162 bf162;

// ---------------- scratch ----------------
__device__ __align__(16) bf16 g_wt[768 * 256 + 3 * 256 * 256]; // bf16 weights

#define WT_QKV  0
#define WT_PROJ (768 * 256)
#define WT_FC1  (WT_PROJ + 256 * 256)
#define WT_FC2  (WT_FC1 + 256 * 256)

// ---------------- helpers ----------------
__device__ __forceinline__ uint32_t smem_u32(const void* p) {
    uint32_t a;
    asm("{ .reg .u64 t; cvta.to.shared.u64 t, %1; cvt.u32.u64 %0, t; }" : "=r"(a) : "l"(p));
    return a;
}
__device__ __forceinline__ void mma_bf16(float c[4],
                                         uint32_t a0, uint32_t a1, uint32_t a2, uint32_t a3,
                                         uint32_t b0, uint32_t b1) {
    asm volatile(
        "mma.sync.aligned.m16n8k16.row.col.f32.bf16.bf16.f32 "
        "{%0,%1,%2,%3}, {%4,%5,%6,%7}, {%8,%9}, {%0,%1,%2,%3};"
        : "+f"(c[0]), "+f"(c[1]), "+f"(c[2]), "+f"(c[3])
        : "r"(a0), "r"(a1), "r"(a2), "r"(a3), "r"(b0), "r"(b1));
}
__device__ __forceinline__ void ldsm_x4(uint32_t& r0, uint32_t& r1, uint32_t& r2, uint32_t& r3,
                                        uint32_t addr) {
    asm volatile("ldmatrix.sync.aligned.m8n8.x4.shared.b16 {%0,%1,%2,%3}, [%4];"
        : "=r"(r0), "=r"(r1), "=r"(r2), "=r"(r3) : "r"(addr));
}
__device__ __forceinline__ void ldsm_x2(uint32_t& r0, uint32_t& r1, uint32_t addr) {
    asm volatile("ldmatrix.sync.aligned.m8n8.x2.shared.b16 {%0,%1}, [%2];"
        : "=r"(r0), "=r"(r1) : "r"(addr));
}
__device__ __forceinline__ uint32_t pack_bf16(float x, float y) {
    bf162 v = __floats2bfloat162_rn(x, y);
    return *(uint32_t*)&v;
}
#define CP16(dst, src) \
    asm volatile("cp.async.cg.shared.global [%0], [%1], 16;" :: "r"(dst), "l"(src) : "memory")
#define CP_COMMIT() asm volatile("cp.async.commit_group;" ::: "memory")
#define CP_WAIT1()  asm volatile("cp.async.wait_group 1;" ::: "memory")
#define CP_WAIT0()  asm volatile("cp.async.wait_group 0;" ::: "memory")

// windowed row -> original token row (reverse shift)
__device__ __forceinline__ long unwin_row(long wr) {
    int batch = (int)(wr >> 14);
    int win   = ((int)wr >> 6) & 255;
    int token = (int)wr & 63;
    int ys = ((win >> 4) << 3) + (token >> 3);
    int xs = ((win & 15) << 3) + (token & 7);
    int y  = (ys + SSHIFT) & 127;
    int xx = (xs + SSHIFT) & 127;
    return (long)batch * 16384 + y * 128 + xx;
}

// ================ smem layout (bytes) ================
#define M_TILEA 0
#define M_B     33792
#define M_QS    86016
#define M_KS    91136
#define M_VST   96256
#define M_PS    100864
#define M_LUT   110080
#define M_QB    111104
#define M_RED   111104
#define M_SMEM  114176

__global__ __launch_bounds__(256, 2)
void swin_block(const float* __restrict__ x,
                const float* __restrict__ g1, const float* __restrict__ b1v,
                const bf16* __restrict__ Wt3, const float* __restrict__ qkvb,
                const float* __restrict__ rel_bias,
                const bf16* __restrict__ Wp, const float* __restrict__ pbias,
                const float* __restrict__ g2, const float* __restrict__ b2,
                const bf16* __restrict__ W1, const float* __restrict__ fb1,
                const bf16* __restrict__ W2, const float* __restrict__ fb2,
                float* __restrict__ out)
{
    extern __shared__ char smc[];
    float*    smF = (float*)smc;
    uint32_t* smW = (uint32_t*)smc;
    bf16*     smH = (bf16*)smc;
    uint32_t  sm0 = smem_u32(smc);

    int tid = threadIdx.x, warp = tid >> 5, lane = tid & 31;
    int g = lane >> 2, t = lane & 3;
    int lr  = lane & 7;
    int x4r = lr + ((lane >> 3) & 1) * 8;
    int x4c = ((lane >> 4) & 1) * 4;
    int x2c = ((lane >> 3) & 1) * 4;
    int bx4r = lr + ((lane >> 4) & 1) * 8;
    int bx4c = ((lane >> 3) & 1) * 4;
    long bm = (long)blockIdx.x * 64;
    const int lrow = tid >> 2, lch = (tid & 3) * 8;

    float* qb  = smF + M_QB / 4;
    float* lut = smF + M_LUT / 4;

    #pragma unroll
    for (int i = 0; i < 3; i++) qb[tid + i * 256] = qkvb[tid + i * 256];

    auto loadB1 = [&](int buf, int h, int kc) {
        uint32_t Bs = sm0 + M_B + buf * 26112;
        const bf16* src = Wt3 + (size_t)h * 96 * 256 + kc * 128;
        #pragma unroll
        for (int i = 0; i < 6; i++) {
            int e = tid + i * 256;
            int row = e >> 4, c8 = (e & 15) * 8;
            CP16(Bs + row * 272 + c8 * 2, src + row * 256 + c8);
        }
    };
    // block2 weight stage (BK=32, 20480 B/stage) — proven R12/R13 layout
    auto loadW = [&](int buf, int k0, const bf16* W) {
        uint32_t Bs = sm0 + M_B + buf * 20480;
        #pragma unroll
        for (int i = 0; i < 4; i++) {
            int row = lrow + i * 64;
            CP16(Bs + row * 80 + lch * 2, W + (size_t)row * 256 + k0 + lch);
        }
    };

    loadB1(0, 0, 0); CP_COMMIT();
    loadB1(1, 0, 1); CP_COMMIT();

    // ---- LN1 + shifted-window gather into tileA ----
    for (int i = 0; i < 8; i++) {
        int r = warp * 8 + i;
        long srow = unwin_row(bm + r);
        const float4* px = (const float4*)(x + srow * 256);
        float4 v0 = px[lane * 2], v1 = px[lane * 2 + 1];
        float s  = v0.x + v0.y + v0.z + v0.w + v1.x + v1.y + v1.z + v1.w;
        float s2 = v0.x*v0.x + v0.y*v0.y + v0.z*v0.z + v0.w*v0.w
                 + v1.x*v1.x + v1.y*v1.y + v1.z*v1.z + v1.w*v1.w;
        #pragma unroll
        for (int o = 16; o > 0; o >>= 1) {
            s  += __shfl_xor_sync(0xffffffffu, s,  o);
            s2 += __shfl_xor_sync(0xffffffffu, s2, o);
        }
        float mean = s * (1.0f / 256.0f);
        float inv = rsqrtf(s2 * (1.0f / 256.0f) - mean * mean + EPS_F);
        float4 ga = *(const float4*)(g1 + lane * 8);
        float4 gb = *(const float4*)(g1 + lane * 8 + 4);
        float4 ba = *(const float4*)(b1v + lane * 8);
        float4 bb = *(const float4*)(b1v + lane * 8 + 4);
        uint4 o4;
        o4.x = pack_bf16((v0.x - mean) * inv * ga.x + ba.x, (v0.y - mean) * inv * ga.y + ba.y);
        o4.y = pack_bf16((v0.z - mean) * inv * ga.z + ba.z, (v0.w - mean) * inv * ga.w + ba.w);
        o4.z = pack_bf16((v1.x - mean) * inv * gb.x + bb.x, (v1.y - mean) * inv * gb.y + bb.y);
        o4.w = pack_bf16((v1.z - mean) * inv * gb.z + bb.z, (v1.w - mean) * inv * gb.w + bb.w);
        *(uint4*)(smH + r * 264 + lane * 8) = o4;
    }

    int wmq = (warp & 3) * 16;
    int wnq = (warp >> 2) * 48;

    uint32_t oacc[8][4];      // per-head PV output (packed bf16 pairs)

    #pragma unroll 1
    for (int h = 0; h < 8; h++) {
        CP_WAIT1();
        __syncthreads();

        // lut for head h: hoisted so its latency hides under the GEMM
        if (tid < 225) lut[tid] = rel_bias[tid * 8 + h];

        // ---- qkv GEMM for head h: 64x96x256 ----
        float c[6][4];
        #pragma unroll
        for (int ni = 0; ni < 6; ni++)
            #pragma unroll
            for (int r = 0; r < 4; r++) c[ni][r] = 0.f;

        #pragma unroll
        for (int kc = 0; kc < 2; kc++) {
            if (kc == 1) CP_WAIT0();
            uint32_t Bb = sm0 + M_B + kc * 26112;
            #pragma unroll
            for (int ks = 0; ks < 8; ks++) {
                int kw = ks * 8;
                uint32_t a0, a1, a2, a3;
                ldsm_x4(a0, a1, a2, a3,
                        sm0 + ((wmq + x4r) * 132 + kc * 64 + kw + x4c) * 4);
                #pragma unroll
                for (int ni = 0; ni < 6; ni++) {
                    uint32_t b0, b1;
                    ldsm_x2(b0, b1, Bb + ((wnq + ni * 8 + lr) * 68 + kw + x2c) * 4);
                    mma_bf16(c[ni], a0, a1, a2, a3, b0, b1);
                }
            }
        }

        // ---- stage q/k/v (+bias): branch-free per warp half ----
        {
            int lr0 = wmq + g, lr1 = lr0 + 8;
            if (warp < 4) {
                #pragma unroll
                for (int ni = 0; ni < 4; ni++) {
                    int cj = ni * 8 + 2 * t;
                    float bb0 = qb[h * 32 + cj], bb1 = qb[h * 32 + cj + 1];
                    smW[M_QS / 4 + lr0 * 20 + (cj >> 1)] = pack_bf16(c[ni][0] + bb0, c[ni][1] + bb1);
                    smW[M_QS / 4 + lr1 * 20 + (cj >> 1)] = pack_bf16(c[ni][2] + bb0, c[ni][3] + bb1);
                }
                #pragma unroll
                for (int ni = 4; ni < 6; ni++) {
                    int cj = (ni - 4) * 8 + 2 * t;
                    float bb0 = qb[256 + h * 32 + cj], bb1 = qb[256 + h * 32 + cj + 1];
                    smW[M_KS / 4 + lr0 * 20 + (cj >> 1)] = pack_bf16(c[ni][0] + bb0, c[ni][1] + bb1);
                    smW[M_KS / 4 + lr1 * 20 + (cj >> 1)] = pack_bf16(c[ni][2] + bb0, c[ni][3] + bb1);
                }
            } else {
                #pragma unroll
                for (int ni = 0; ni < 2; ni++) {
                    int cj = 16 + ni * 8 + 2 * t;
                    float bb0 = qb[256 + h * 32 + cj], bb1 = qb[256 + h * 32 + cj + 1];
                    smW[M_KS / 4 + lr0 * 20 + (cj >> 1)] = pack_bf16(c[ni][0] + bb0, c[ni][1] + bb1);
                    smW[M_KS / 4 + lr1 * 20 + (cj >> 1)] = pack_bf16(c[ni][2] + bb0, c[ni][3] + bb1);
                }
                bf16* ve = smH + M_VST / 2;
                #pragma unroll
                for (int ni = 2; ni < 6; ni++) {
                    int cj = (ni - 2) * 8 + 2 * t;
                    float bb0 = qb[512 + h * 32 + cj], bb1 = qb[512 + h * 32 + cj + 1];
                    ve[cj * 72 + lr0]       = __float2bfloat16_rn(c[ni][0] + bb0);
                    ve[(cj + 1) * 72 + lr0] = __float2bfloat16_rn(c[ni][1] + bb1);
                    ve[cj * 72 + lr1]       = __float2bfloat16_rn(c[ni][2] + bb0);
                    ve[(cj + 1) * 72 + lr1] = __float2bfloat16_rn(c[ni][3] + bb1);
                }
            }
        }
        __syncthreads();

        if (h < 7) {
            loadB1(0, h + 1, 0); CP_COMMIT();
            loadB1(1, h + 1, 1); CP_COMMIT();
        } else {
            // qkv B stages dead: prefetch proj L0/L1 (hides under softmax+PV+dump).
            // Buffers 0/1 (33792..74752) don't touch QS/KS/VST/PS still in use.
            loadW(0, 0, Wp);  CP_COMMIT();
            loadW(1, 32, Wp); CP_COMMIT();
        }

        // ---- QK + softmax: warps 0..3 ----
        if (warp < 4) {
            int wm2 = warp * 16;
            float s[8][4];
            #pragma unroll
            for (int ni = 0; ni < 8; ni++)
                #pragma unroll
                for (int r = 0; r < 4; r++) s[ni][r] = 0.f;

            #pragma unroll
            for (int kt = 0; kt < 2; kt++) {
                int kw = kt * 8;
                uint32_t a0, a1, a2, a3;
                ldsm_x4(a0, a1, a2, a3,
                        sm0 + M_QS + ((wm2 + x4r) * 20 + kw + x4c) * 4);
                #pragma unroll
                for (int ni = 0; ni < 8; ni++) {
                    uint32_t b0, b1;
                    ldsm_x2(b0, b1, sm0 + M_KS + ((ni * 8 + lr) * 20 + kw + x2c) * 4);
                    mma_bf16(s[ni], a0, a1, a2, a3, b0, b1);
                }
            }

            int r0 = wm2 + g, r1 = wm2 + g + 8;
            int rh0 = r0 >> 3, rw0 = r0 & 7;
            int rh1 = r1 >> 3, rw1 = r1 & 7;
            float mx0 = -1e30f, mx1 = -1e30f;
            #pragma unroll
            for (int ni = 0; ni < 8; ni++) {
                #pragma unroll
                for (int cc2 = 0; cc2 < 2; cc2++) {
                    int col = ni * 8 + 2 * t + cc2;
                    int mh = col >> 3, mw = col & 7;
                    s[ni][cc2]     = s[ni][cc2]     * SCALE_F + lut[(rh0 - mh + 7) * 15 + (rw0 - mw + 7)];
                    s[ni][2 + cc2] = s[ni][2 + cc2] * SCALE_F + lut[(rh1 - mh + 7) * 15 + (rw1 - mw + 7)];
                    mx0 = fmaxf(mx0, s[ni][cc2]);
                    mx1 = fmaxf(mx1, s[ni][2 + cc2]);
                }
            }
            mx0 = fmaxf(mx0, __shfl_xor_sync(0xffffffffu, mx0, 1));
            mx0 = fmaxf(mx0, __shfl_xor_sync(0xffffffffu, mx0, 2));
            mx1 = fmaxf(mx1, __shfl_xor_sync(0xffffffffu, mx1, 1));
            mx1 = fmaxf(mx1, __shfl_xor_sync(0xffffffffu, mx1, 2));
            float sum0 = 0.f, sum1 = 0.f;
            #pragma unroll
            for (int ni = 0; ni < 8; ni++) {
                s[ni][0] = __expf(s[ni][0] - mx0); sum0 += s[ni][0];
                s[ni][1] = __expf(s[ni][1] - mx0); sum0 += s[ni][1];
                s[ni][2] = __expf(s[ni][2] - mx1); sum1 += s[ni][2];
                s[ni][3] = __expf(s[ni][3] - mx1); sum1 += s[ni][3];
            }
            sum0 += __shfl_xor_sync(0xffffffffu, sum0, 1);
            sum0 += __shfl_xor_sync(0xffffffffu, sum0, 2);
            sum1 += __shfl_xor_sync(0xffffffffu, sum1, 1);
            sum1 += __shfl_xor_sync(0xffffffffu, sum1, 2);
            float inv0 = 1.0f / sum0, inv1 = 1.0f / sum1;
            #pragma unroll
            for (int ni = 0; ni < 8; ni++) {
                smW[M_PS / 4 + r0 * 36 + ni * 4 + t] = pack_bf16(s[ni][0] * inv0, s[ni][1] * inv0);
                smW[M_PS / 4 + r1 * 36 + ni * 4 + t] = pack_bf16(s[ni][2] * inv1, s[ni][3] * inv1);
            }
        }
        __syncthreads();

        // ---- PV: all 8 warps, 16 rows x 16 cols -> oacc ----
        {
            int rowb = (warp & 3) * 16, colb = (warp >> 2) * 16;
            float o[2][4];
            #pragma unroll
            for (int ni = 0; ni < 2; ni++)
                #pragma unroll
                for (int r = 0; r < 4; r++) o[ni][r] = 0.f;
            #pragma unroll
            for (int kt = 0; kt < 4; kt++) {
                int kw = kt * 8;
                uint32_t a0, a1, a2, a3;
                ldsm_x4(a0, a1, a2, a3,
                        sm0 + M_PS + ((rowb + x4r) * 36 + kw + x4c) * 4);
                #pragma unroll
                for (int ni = 0; ni < 2; ni++) {
                    uint32_t b0, b1;
                    ldsm_x2(b0, b1, sm0 + M_VST + ((colb + ni * 8 + lr) * 36 + kw + x2c) * 4);
                    mma_bf16(o[ni], a0, a1, a2, a3, b0, b1);
                }
            }
            #pragma unroll
            for (int ni = 0; ni < 2; ni++) {
                oacc[h][ni * 2]     = pack_bf16(o[ni][0], o[ni][1]);
                oacc[h][ni * 2 + 1] = pack_bf16(o[ni][2], o[ni][3]);
            }
        }
    }

    // ---- dump attn out into tileA (LN1 data dead) ----
    __syncthreads();
    {
        int rowb = (warp & 3) * 16, colb = (warp >> 2) * 16;
        #pragma unroll
        for (int h = 0; h < 8; h++) {
            #pragma unroll
            for (int ni = 0; ni < 2; ni++) {
                int wcol = h * 16 + (colb >> 1) + ni * 4 + t;
                smW[(rowb + g) * 132 + wcol]     = oacc[h][ni * 2];
                smW[(rowb + g + 8) * 132 + wcol] = oacc[h][ni * 2 + 1];
            }
        }
    }
    __syncthreads();

    // ================== block2 phases ==================
    int wm = (warp & 1) * 32, wn = (warp >> 1) * 64, wnid = warp >> 1;
    float* red = smF + M_RED / 4;

    int lr0[2], lr1[2];
    long t0[2], t1[2];
    #pragma unroll
    for (int mi = 0; mi < 2; mi++) {
        lr0[mi] = wm + mi * 16 + g;
        lr1[mi] = lr0[mi] + 8;
        t0[mi] = unwin_row(bm + lr0[mi]);
        t1[mi] = unwin_row(bm + lr1[mi]);
    }

    float c[2][8][4];

    auto compS = [&](int buf, int itk) {
        uint32_t Bb = sm0 + M_B + buf * 20480;
        #pragma unroll
        for (int kt = 0; kt < 2; kt++) {
            int kwg = itk * 16 + kt * 8;
            int kw = kt * 8;
            uint32_t a[2][4];
            #pragma unroll
            for (int mi = 0; mi < 2; mi++)
                ldsm_x4(a[mi][0], a[mi][1], a[mi][2], a[mi][3],
                        sm0 + ((wm + mi * 16 + x4r) * 132 + kwg + x4c) * 4);
            #pragma unroll
            for (int np = 0; np < 4; np++) {
                uint32_t b0, b1, b2, b3;
                ldsm_x4(b0, b1, b2, b3,
                        Bb + ((wn + np * 16 + bx4r) * 20 + kw + bx4c) * 4);
                mma_bf16(c[0][2*np],   a[0][0], a[0][1], a[0][2], a[0][3], b0, b1);
                mma_bf16(c[1][2*np],   a[1][0], a[1][1], a[1][2], a[1][3], b0, b1);
                mma_bf16(c[0][2*np+1], a[0][0], a[0][1], a[0][2], a[0][3], b2, b3);
                mma_bf16(c[1][2*np+1], a[1][0], a[1][1], a[1][2], a[1][3], b2, b3);
            }
        }
    };
    auto zeroC = [&]() {
        #pragma unroll
        for (int mi = 0; mi < 2; mi++)
            #pragma unroll
            for (int ni = 0; ni < 8; ni++)
                #pragma unroll
                for (int r = 0; r < 4; r++) c[mi][ni][r] = 0.f;
    };
    auto run_phase = [&](const bf16* W, bool pre) {
        zeroC();
        if (!pre) {
            loadW(0, 0, W); CP_COMMIT();
            loadW(1, 32, W); CP_COMMIT();
        }
        CP_WAIT1();
        __syncthreads();
        for (int it = 0; it < 8; ++it) {
            if (it + 2 < 8) loadW((it + 2) % 3, (it + 2) * 32, W);
            CP_COMMIT();
            compS(it % 3, it);
            CP_WAIT1();
            __syncthreads();
        }
    };

    // ---- phase 1: proj (A = attn out in tileA; L0/L1 prefetched at head 7) ----
    run_phase(Wp, true);
    {
        float s0[2] = {0.f, 0.f}, q0[2] = {0.f, 0.f};
        float s1[2] = {0.f, 0.f}, q1[2] = {0.f, 0.f};
        #pragma unroll
        for (int mi = 0; mi < 2; mi++) {
            #pragma unroll
            for (int ni = 0; ni < 8; ni++) {
                int col = wn + ni * 8 + 2 * t;
                float b0 = pbias[col], b1 = pbias[col + 1];
                float2 ra = *(const float2*)(x + t0[mi] * 256 + col);
                float2 rb = *(const float2*)(x + t1[mi] * 256 + col);
                float v0 = c[mi][ni][0] + b0 + ra.x;
                float v1 = c[mi][ni][1] + b1 + ra.y;
                float v2 = c[mi][ni][2] + b0 + rb.x;
                float v3 = c[mi][ni][3] + b1 + rb.y;
                *(float2*)(out + t0[mi] * 256 + col) = make_float2(v0, v1);
                *(float2*)(out + t1[mi] * 256 + col) = make_float2(v2, v3);
                c[mi][ni][0] = v0; c[mi][ni][1] = v1;
                c[mi][ni][2] = v2; c[mi][ni][3] = v3;
                s0[mi] += v0 + v1; q0[mi] += v0 * v0 + v1 * v1;
                s1[mi] += v2 + v3; q1[mi] += v2 * v2 + v3 * v3;
            }
        }
        #pragma unroll
        for (int o = 1; o < 4; o <<= 1) {
            #pragma unroll
            for (int mi = 0; mi < 2; mi++) {
                s0[mi] += __shfl_xor_sync(0xffffffffu, s0[mi], o);
                q0[mi] += __shfl_xor_sync(0xffffffffu, q0[mi], o);
                s1[mi] += __shfl_xor_sync(0xffffffffu, s1[mi], o);
                q1[mi] += __shfl_xor_sync(0xffffffffu, q1[mi], o);
            }
        }
        if (t == 0) {
            #pragma unroll
            for (int mi = 0; mi < 2; mi++) {
                red[lr0[mi] * 8 + wnid * 2]     = s0[mi];
                red[lr0[mi] * 8 + wnid * 2 + 1] = q0[mi];
                red[lr1[mi] * 8 + wnid * 2]     = s1[mi];
                red[lr1[mi] * 8 + wnid * 2 + 1] = q1[mi];
            }
        }
        __syncthreads();
        #pragma unroll
        for (int mi = 0; mi < 2; mi++) {
            float sa = 0.f, qa = 0.f, sb = 0.f, qb2 = 0.f;
            #pragma unroll
            for (int j = 0; j < 4; j++) {
                sa  += red[lr0[mi] * 8 + j * 2];
                qa  += red[lr0[mi] * 8 + j * 2 + 1];
                sb  += red[lr1[mi] * 8 + j * 2];
                qb2 += red[lr1[mi] * 8 + j * 2 + 1];
            }
            float m0 = sa * (1.0f / 256.0f);
            float i0 = rsqrtf(qa * (1.0f / 256.0f) - m0 * m0 + EPS_F);
            float m1 = sb * (1.0f / 256.0f);
            float i1 = rsqrtf(qb2 * (1.0f / 256.0f) - m1 * m1 + EPS_F);
            #pragma unroll
            for (int ni = 0; ni < 8; ni++) {
                int col = wn + ni * 8 + 2 * t;
                float2 gg = *(const float2*)(g2 + col);
                float2 bb = *(const float2*)(b2 + col);
                smW[lr0[mi] * 132 + (col >> 1)] =
                    pack_bf16((c[mi][ni][0] - m0) * i0 * gg.x + bb.x,
                              (c[mi][ni][1] - m0) * i0 * gg.y + bb.y);
                smW[lr1[mi] * 132 + (col >> 1)] =
                    pack_bf16((c[mi][ni][2] - m1) * i1 * gg.x + bb.x,
                              (c[mi][ni][3] - m1) * i1 * gg.y + bb.y);
            }
        }
    }
    __syncthreads();

    // ---- phase 2: fc1 + GELU ----
    run_phase(W1, false);
    #pragma unroll
    for (int mi = 0; mi < 2; mi++) {
        #pragma unroll
        for (int ni = 0; ni < 8; ni++) {
            int col = wn + ni * 8 + 2 * t;
            float b0 = fb1[col], b1 = fb1[col + 1];
            float v0 = c[mi][ni][0] + b0;
            float v1 = c[mi][ni][1] + b1;
            float v2 = c[mi][ni][2] + b0;
            float v3 = c[mi][ni][3] + b1;
            v0 = 0.5f * v0 * (1.0f + erff(v0 * 0.70710678118654752f));
            v1 = 0.5f * v1 * (1.0f + erff(v1 * 0.70710678118654752f));
            v2 = 0.5f * v2 * (1.0f + erff(v2 * 0.70710678118654752f));
            v3 = 0.5f * v3 * (1.0f + erff(v3 * 0.70710678118654752f));
            smW[lr0[mi] * 132 + (col >> 1)] = pack_bf16(v0, v1);
            smW[lr1[mi] * 132 + (col >> 1)] = pack_bf16(v2, v3);
        }
    }
    __syncthreads();

    // ---- phase 3: fc2 + residual (x2 re-read from out) ----
    run_phase(W2, false);
    #pragma unroll
    for (int mi = 0; mi < 2; mi++) {
        #pragma unroll
        for (int ni = 0; ni < 8; ni++) {
            int col = wn + ni * 8 + 2 * t;
            float b0 = fb2[col], b1 = fb2[col + 1];
            float2 ra = *(const float2*)(out + t0[mi] * 256 + col);
            float2 rb = *(const float2*)(out + t1[mi] * 256 + col);
            *(float2*)(out + t0[mi] * 256 + col) =
                make_float2(c[mi][ni][0] + b0 + ra.x, c[mi][ni][1] + b1 + ra.y);
            *(float2*)(out + t1[mi] * 256 + col) =
                make_float2(c[mi][ni][2] + b0 + rb.x, c[mi][ni][3] + b1 + rb.y);
        }
    }
}

// ================ merged weight convert (single launch) ================
__global__ void cvt_all(const float* __restrict__ qkv_w, const float* __restrict__ proj_w,
                        const float* __restrict__ fc1_w, const float* __restrict__ fc2_w,
                        bf16* __restrict__ wt)
{
    __shared__ float tsm[32][33];
    int bx = blockIdx.x;
    int k0 = blockIdx.y * 32;
    int tx = threadIdx.x, ty = threadIdx.y;
    if (bx < 24) {
        int n0 = bx * 32;
        int n = n0 + tx;
        int h = n / 96, j = n % 96;
        int cidx = (j >> 5) * 256 + h * 32 + (j & 31);
        tsm[ty][tx] = qkv_w[(size_t)(k0 + ty) * 768 + cidx];
        __syncthreads();
        wt[WT_QKV + (size_t)(n0 + ty) * 256 + k0 + tx] = __float2bfloat16_rn(tsm[tx][ty]);
    } else {
        int s = (bx - 24) >> 3;
        int n0 = ((bx - 24) & 7) * 32;
        const float* W = (s == 0) ? proj_w : ((s == 1) ? fc1_w : fc2_w);
        size_t base = (s == 0) ? WT_PROJ : ((s == 1) ? WT_FC1 : WT_FC2);
        tsm[ty][tx] = W[(size_t)(k0 + ty) * 256 + n0 + tx];
        __syncthreads();
        wt[base + (size_t)(n0 + ty) * 256 + k0 + tx] = __float2bfloat16_rn(tsm[tx][ty]);
    }
}

// ---------------- launch ----------------
extern "C" void kernel_launch(void* const* d_in, const int* in_sizes, int n_in,
                              void* d_out, int out_size)
{
    const float* x       = (const float*)d_in[0];
    const float* norm1_g = (const float*)d_in[1];
    const float* norm1_b = (const float*)d_in[2];
    const float* qkv_w   = (const float*)d_in[3];
    const float* qkv_b   = (const float*)d_in[4];
    const float* rel_b   = (const float*)d_in[5];
    const float* proj_w  = (const float*)d_in[6];
    const float* proj_b  = (const float*)d_in[7];
    const float* norm2_g = (const float*)d_in[8];
    const float* norm2_b = (const float*)d_in[9];
    const float* fc1_w   = (const float*)d_in[10];
    const float* fc1_b   = (const float*)d_in[11];
    const float* fc2_w   = (const float*)d_in[12];
    const float* fc2_b   = (const float*)d_in[13];
    float* out = (float*)d_out;

    bf16* p_wt;
    cudaGetSymbolAddress((void**)&p_wt, g_wt);

    cudaFuncSetAttribute(swin_block, cudaFuncAttributeMaxDynamicSharedMemorySize, M_SMEM);

    // 0) merged weight convert
    cvt_all<<<dim3(48, 8), dim3(32, 32)>>>(qkv_w, proj_w, fc1_w, fc2_w, p_wt);

    // 1) whole Swin block in one kernel: one window per CTA
    swin_block<<<NWIN, 256, M_SMEM>>>(
        x, norm1_g, norm1_b, p_wt + WT_QKV, qkv_b, rel_b,
        p_wt + WT_PROJ, proj_b, norm2_g, norm2_b,
        p_wt + WT_FC1, fc1_b, p_wt + WT_FC2, fc2_b, out);
}

// round 16
// speedup vs baseline: 1.2324x; 1.0127x over previous
#include <cuda_runtime.h>
#include <cuda_bf16.h>
#include <math.h>
#include <stdint.h>

// ---------------- problem constants ----------------
#define CC      256
#define NHEAD   8
#define HDIM    32
#define SSHIFT  4
#define NWIN    2048
#define TTOT    131072
#define SCALE_F 0.1767766952966369f
#define EPS_F   1e-5f

typedef __nv_bfloat16 bf16;
typedef __nv_bfloat162 bf162;

// ---------------- scratch ----------------
__device__ __align__(16) bf16 g_wt[768 * 256 + 3 * 256 * 256]; // bf16 weights

#define WT_QKV  0
#define WT_PROJ (768 * 256)
#define WT_FC1  (WT_PROJ + 256 * 256)
#define WT_FC2  (WT_FC1 + 256 * 256)

// ---------------- helpers ----------------
__device__ __forceinline__ uint32_t smem_u32(const void* p) {
    uint32_t a;
    asm("{ .reg .u64 t; cvta.to.shared.u64 t, %1; cvt.u32.u64 %0, t; }" : "=r"(a) : "l"(p));
    return a;
}
__device__ __forceinline__ void mma_bf16(float c[4],
                                         uint32_t a0, uint32_t a1, uint32_t a2, uint32_t a3,
                                         uint32_t b0, uint32_t b1) {
    asm volatile(
        "mma.sync.aligned.m16n8k16.row.col.f32.bf16.bf16.f32 "
        "{%0,%1,%2,%3}, {%4,%5,%6,%7}, {%8,%9}, {%0,%1,%2,%3};"
        : "+f"(c[0]), "+f"(c[1]), "+f"(c[2]), "+f"(c[3])
        : "r"(a0), "r"(a1), "r"(a2), "r"(a3), "r"(b0), "r"(b1));
}
__device__ __forceinline__ void ldsm_x4(uint32_t& r0, uint32_t& r1, uint32_t& r2, uint32_t& r3,
                                        uint32_t addr) {
    asm volatile("ldmatrix.sync.aligned.m8n8.x4.shared.b16 {%0,%1,%2,%3}, [%4];"
        : "=r"(r0), "=r"(r1), "=r"(r2), "=r"(r3) : "r"(addr));
}
__device__ __forceinline__ void ldsm_x2(uint32_t& r0, uint32_t& r1, uint32_t addr) {
    asm volatile("ldmatrix.sync.aligned.m8n8.x2.shared.b16 {%0,%1}, [%2];"
        : "=r"(r0), "=r"(r1) : "r"(addr));
}
__device__ __forceinline__ uint32_t pack_bf16(float x, float y) {
    bf162 v = __floats2bfloat162_rn(x, y);
    return *(uint32_t*)&v;
}
#define CP16(dst, src) \
    asm volatile("cp.async.cg.shared.global [%0], [%1], 16;" :: "r"(dst), "l"(src) : "memory")
#define CP_COMMIT() asm volatile("cp.async.commit_group;" ::: "memory")
#define CP_WAIT1()  asm volatile("cp.async.wait_group 1;" ::: "memory")
#define CP_WAIT0()  asm volatile("cp.async.wait_group 0;" ::: "memory")

// windowed row -> original token row (reverse shift)
__device__ __forceinline__ long unwin_row(long wr) {
    int batch = (int)(wr >> 14);
    int win   = ((int)wr >> 6) & 255;
    int token = (int)wr & 63;
    int ys = ((win >> 4) << 3) + (token >> 3);
    int xs = ((win & 15) << 3) + (token & 7);
    int y  = (ys + SSHIFT) & 127;
    int xx = (xs + SSHIFT) & 127;
    return (long)batch * 16384 + y * 128 + xx;
}

// ================ smem layout (bytes) ================
#define M_TILEA 0
#define M_B     33792
#define M_QS    86016
#define M_KS    91136
#define M_VST   96256
#define M_PS    100864
#define M_LUT   110080
#define M_QB    111104
#define M_RED   111104
#define M_SMEM  114176

__global__ __launch_bounds__(256, 2)
void swin_block(const float* __restrict__ x,
                const float* __restrict__ g1, const float* __restrict__ b1v,
                const bf16* __restrict__ Wt3, const float* __restrict__ qkvb,
                const float* __restrict__ rel_bias,
                const bf16* __restrict__ Wp, const float* __restrict__ pbias,
                const float* __restrict__ g2, const float* __restrict__ b2,
                const bf16* __restrict__ W1, const float* __restrict__ fb1,
                const bf16* __restrict__ W2, const float* __restrict__ fb2,
                float* __restrict__ out)
{
    extern __shared__ char smc[];
    float*    smF = (float*)smc;
    uint32_t* smW = (uint32_t*)smc;
    bf16*     smH = (bf16*)smc;
    uint32_t  sm0 = smem_u32(smc);

    int tid = threadIdx.x, warp = tid >> 5, lane = tid & 31;
    int g = lane >> 2, t = lane & 3;
    int lr  = lane & 7;
    int x4r = lr + ((lane >> 3) & 1) * 8;
    int x4c = ((lane >> 4) & 1) * 4;
    int x2c = ((lane >> 3) & 1) * 4;
    int bx4r = lr + ((lane >> 4) & 1) * 8;
    int bx4c = ((lane >> 3) & 1) * 4;
    long bm = (long)blockIdx.x * 64;
    const int lrow = tid >> 2, lch = (tid & 3) * 8;

    float* qb  = smF + M_QB / 4;
    float* lut = smF + M_LUT / 4;

    #pragma unroll
    for (int i = 0; i < 3; i++) qb[tid + i * 256] = qkvb[tid + i * 256];

    auto loadB1 = [&](int buf, int h, int kc) {
        uint32_t Bs = sm0 + M_B + buf * 26112;
        const bf16* src = Wt3 + (size_t)h * 96 * 256 + kc * 128;
        #pragma unroll
        for (int i = 0; i < 6; i++) {
            int e = tid + i * 256;
            int row = e >> 4, c8 = (e & 15) * 8;
            CP16(Bs + row * 272 + c8 * 2, src + row * 256 + c8);
        }
    };
    auto loadW = [&](int buf, int k0, const bf16* W) {
        uint32_t Bs = sm0 + M_B + buf * 20480;
        #pragma unroll
        for (int i = 0; i < 4; i++) {
            int row = lrow + i * 64;
            CP16(Bs + row * 80 + lch * 2, W + (size_t)row * 256 + k0 + lch);
        }
    };

    loadB1(0, 0, 0); CP_COMMIT();
    loadB1(1, 0, 1); CP_COMMIT();

    // ---- LN1 + shifted-window gather into tileA ----
    for (int i = 0; i < 8; i++) {
        int r = warp * 8 + i;
        long srow = unwin_row(bm + r);
        const float4* px = (const float4*)(x + srow * 256);
        float4 v0 = px[lane * 2], v1 = px[lane * 2 + 1];
        float s  = v0.x + v0.y + v0.z + v0.w + v1.x + v1.y + v1.z + v1.w;
        float s2 = v0.x*v0.x + v0.y*v0.y + v0.z*v0.z + v0.w*v0.w
                 + v1.x*v1.x + v1.y*v1.y + v1.z*v1.z + v1.w*v1.w;
        #pragma unroll
        for (int o = 16; o > 0; o >>= 1) {
            s  += __shfl_xor_sync(0xffffffffu, s,  o);
            s2 += __shfl_xor_sync(0xffffffffu, s2, o);
        }
        float mean = s * (1.0f / 256.0f);
        float inv = rsqrtf(s2 * (1.0f / 256.0f) - mean * mean + EPS_F);
        float4 ga = *(const float4*)(g1 + lane * 8);
        float4 gb = *(const float4*)(g1 + lane * 8 + 4);
        float4 ba = *(const float4*)(b1v + lane * 8);
        float4 bb = *(const float4*)(b1v + lane * 8 + 4);
        uint4 o4;
        o4.x = pack_bf16((v0.x - mean) * inv * ga.x + ba.x, (v0.y - mean) * inv * ga.y + ba.y);
        o4.y = pack_bf16((v0.z - mean) * inv * ga.z + ba.z, (v0.w - mean) * inv * ga.w + ba.w);
        o4.z = pack_bf16((v1.x - mean) * inv * gb.x + bb.x, (v1.y - mean) * inv * gb.y + bb.y);
        o4.w = pack_bf16((v1.z - mean) * inv * gb.z + bb.z, (v1.w - mean) * inv * gb.w + bb.w);
        *(uint4*)(smH + r * 264 + lane * 8) = o4;
    }

    int wmq = (warp & 3) * 16;
    int wnq = (warp >> 2) * 48;

    uint32_t oacc[8][4];      // per-head PV output (packed bf16 pairs)

    #pragma unroll 1
    for (int h = 0; h < 8; h++) {
        CP_WAIT1();
        __syncthreads();

        // lut for head h: hoisted so its latency hides under the GEMM
        if (tid < 225) lut[tid] = rel_bias[tid * 8 + h];

        // ---- qkv GEMM for head h: 64x96x256 ----
        float c[6][4];
        #pragma unroll
        for (int ni = 0; ni < 6; ni++)
            #pragma unroll
            for (int r = 0; r < 4; r++) c[ni][r] = 0.f;

        #pragma unroll
        for (int kc = 0; kc < 2; kc++) {
            if (kc == 1) CP_WAIT0();
            uint32_t Bb = sm0 + M_B + kc * 26112;
            #pragma unroll
            for (int ks = 0; ks < 8; ks++) {
                int kw = ks * 8;
                uint32_t a0, a1, a2, a3;
                ldsm_x4(a0, a1, a2, a3,
                        sm0 + ((wmq + x4r) * 132 + kc * 64 + kw + x4c) * 4);
                #pragma unroll
                for (int ni = 0; ni < 6; ni++) {
                    uint32_t b0, b1;
                    ldsm_x2(b0, b1, Bb + ((wnq + ni * 8 + lr) * 68 + kw + x2c) * 4);
                    mma_bf16(c[ni], a0, a1, a2, a3, b0, b1);
                }
            }
        }

        // ---- stage q/k/v (+bias): branch-free per warp half ----
        {
            int lr0 = wmq + g, lr1 = lr0 + 8;
            if (warp < 4) {
                #pragma unroll
                for (int ni = 0; ni < 4; ni++) {
                    int cj = ni * 8 + 2 * t;
                    float bb0 = qb[h * 32 + cj], bb1 = qb[h * 32 + cj + 1];
                    smW[M_QS / 4 + lr0 * 20 + (cj >> 1)] = pack_bf16(c[ni][0] + bb0, c[ni][1] + bb1);
                    smW[M_QS / 4 + lr1 * 20 + (cj >> 1)] = pack_bf16(c[ni][2] + bb0, c[ni][3] + bb1);
                }
                #pragma unroll
                for (int ni = 4; ni < 6; ni++) {
                    int cj = (ni - 4) * 8 + 2 * t;
                    float bb0 = qb[256 + h * 32 + cj], bb1 = qb[256 + h * 32 + cj + 1];
                    smW[M_KS / 4 + lr0 * 20 + (cj >> 1)] = pack_bf16(c[ni][0] + bb0, c[ni][1] + bb1);
                    smW[M_KS / 4 + lr1 * 20 + (cj >> 1)] = pack_bf16(c[ni][2] + bb0, c[ni][3] + bb1);
                }
            } else {
                #pragma unroll
                for (int ni = 0; ni < 2; ni++) {
                    int cj = 16 + ni * 8 + 2 * t;
                    float bb0 = qb[256 + h * 32 + cj], bb1 = qb[256 + h * 32 + cj + 1];
                    smW[M_KS / 4 + lr0 * 20 + (cj >> 1)] = pack_bf16(c[ni][0] + bb0, c[ni][1] + bb1);
                    smW[M_KS / 4 + lr1 * 20 + (cj >> 1)] = pack_bf16(c[ni][2] + bb0, c[ni][3] + bb1);
                }
                bf16* ve = smH + M_VST / 2;
                #pragma unroll
                for (int ni = 2; ni < 6; ni++) {
                    int cj = (ni - 2) * 8 + 2 * t;
                    float bb0 = qb[512 + h * 32 + cj], bb1 = qb[512 + h * 32 + cj + 1];
                    ve[cj * 72 + lr0]       = __float2bfloat16_rn(c[ni][0] + bb0);
                    ve[(cj + 1) * 72 + lr0] = __float2bfloat16_rn(c[ni][1] + bb1);
                    ve[cj * 72 + lr1]       = __float2bfloat16_rn(c[ni][2] + bb0);
                    ve[(cj + 1) * 72 + lr1] = __float2bfloat16_rn(c[ni][3] + bb1);
                }
            }
        }
        __syncthreads();

        if (h < 7) {
            loadB1(0, h + 1, 0); CP_COMMIT();
            loadB1(1, h + 1, 1); CP_COMMIT();
        }

        // ---- QK + softmax (no max subtraction; logits bounded): warps 0..3 ----
        if (warp < 4) {
            int wm2 = warp * 16;
            float s[8][4];
            #pragma unroll
            for (int ni = 0; ni < 8; ni++)
                #pragma unroll
                for (int r = 0; r < 4; r++) s[ni][r] = 0.f;

            #pragma unroll
            for (int kt = 0; kt < 2; kt++) {
                int kw = kt * 8;
                uint32_t a0, a1, a2, a3;
                ldsm_x4(a0, a1, a2, a3,
                        sm0 + M_QS + ((wm2 + x4r) * 20 + kw + x4c) * 4);
                #pragma unroll
                for (int ni = 0; ni < 8; ni++) {
                    uint32_t b0, b1;
                    ldsm_x2(b0, b1, sm0 + M_KS + ((ni * 8 + lr) * 20 + kw + x2c) * 4);
                    mma_bf16(s[ni], a0, a1, a2, a3, b0, b1);
                }
            }

            int r0 = wm2 + g, r1 = wm2 + g + 8;
            int rh0 = r0 >> 3, rw0 = r0 & 7;
            int rh1 = r1 >> 3, rw1 = r1 & 7;
            float sum0 = 0.f, sum1 = 0.f;
            #pragma unroll
            for (int ni = 0; ni < 8; ni++) {
                #pragma unroll
                for (int cc2 = 0; cc2 < 2; cc2++) {
                    int col = ni * 8 + 2 * t + cc2;
                    int mh = col >> 3, mw = col & 7;
                    s[ni][cc2]     = __expf(s[ni][cc2]     * SCALE_F + lut[(rh0 - mh + 7) * 15 + (rw0 - mw + 7)]);
                    s[ni][2 + cc2] = __expf(s[ni][2 + cc2] * SCALE_F + lut[(rh1 - mh + 7) * 15 + (rw1 - mw + 7)]);
                    sum0 += s[ni][cc2];
                    sum1 += s[ni][2 + cc2];
                }
            }
            sum0 += __shfl_xor_sync(0xffffffffu, sum0, 1);
            sum0 += __shfl_xor_sync(0xffffffffu, sum0, 2);
            sum1 += __shfl_xor_sync(0xffffffffu, sum1, 1);
            sum1 += __shfl_xor_sync(0xffffffffu, sum1, 2);
            float inv0 = 1.0f / sum0, inv1 = 1.0f / sum1;
            #pragma unroll
            for (int ni = 0; ni < 8; ni++) {
                smW[M_PS / 4 + r0 * 36 + ni * 4 + t] = pack_bf16(s[ni][0] * inv0, s[ni][1] * inv0);
                smW[M_PS / 4 + r1 * 36 + ni * 4 + t] = pack_bf16(s[ni][2] * inv1, s[ni][3] * inv1);
            }
        }
        __syncthreads();

        // ---- PV: all 8 warps, 16 rows x 16 cols -> oacc ----
        {
            int rowb = (warp & 3) * 16, colb = (warp >> 2) * 16;
            float o[2][4];
            #pragma unroll
            for (int ni = 0; ni < 2; ni++)
                #pragma unroll
                for (int r = 0; r < 4; r++) o[ni][r] = 0.f;
            #pragma unroll
            for (int kt = 0; kt < 4; kt++) {
                int kw = kt * 8;
                uint32_t a0, a1, a2, a3;
                ldsm_x4(a0, a1, a2, a3,
                        sm0 + M_PS + ((rowb + x4r) * 36 + kw + x4c) * 4);
                #pragma unroll
                for (int ni = 0; ni < 2; ni++) {
                    uint32_t b0, b1;
                    ldsm_x2(b0, b1, sm0 + M_VST + ((colb + ni * 8 + lr) * 36 + kw + x2c) * 4);
                    mma_bf16(o[ni], a0, a1, a2, a3, b0, b1);
                }
            }
            #pragma unroll
            for (int ni = 0; ni < 2; ni++) {
                oacc[h][ni * 2]     = pack_bf16(o[ni][0], o[ni][1]);
                oacc[h][ni * 2 + 1] = pack_bf16(o[ni][2], o[ni][3]);
            }
        }
    }

    // ---- dump attn out into tileA (no barrier needed: tileA reads are 2
    //      barriers old for every warp; concurrent PV touches only PS/VST) ----
    {
        int rowb = (warp & 3) * 16, colb = (warp >> 2) * 16;
        #pragma unroll
        for (int h = 0; h < 8; h++) {
            #pragma unroll
            for (int ni = 0; ni < 2; ni++) {
                int wcol = h * 16 + (colb >> 1) + ni * 4 + t;
                smW[(rowb + g) * 132 + wcol]     = oacc[h][ni * 2];
                smW[(rowb + g + 8) * 132 + wcol] = oacc[h][ni * 2 + 1];
            }
        }
    }
    __syncthreads();

    // ================== block2 phases ==================
    int wm = (warp & 1) * 32, wn = (warp >> 1) * 64, wnid = warp >> 1;
    float* red = smF + M_RED / 4;

    int lr0[2], lr1[2];
    long t0[2], t1[2];
    #pragma unroll
    for (int mi = 0; mi < 2; mi++) {
        lr0[mi] = wm + mi * 16 + g;
        lr1[mi] = lr0[mi] + 8;
        t0[mi] = unwin_row(bm + lr0[mi]);
        t1[mi] = unwin_row(bm + lr1[mi]);
    }

    float c[2][8][4];

    auto compS = [&](int buf, int itk) {
        uint32_t Bb = sm0 + M_B + buf * 20480;
        #pragma unroll
        for (int kt = 0; kt < 2; kt++) {
            int kwg = itk * 16 + kt * 8;
            int kw = kt * 8;
            uint32_t a[2][4];
            #pragma unroll
            for (int mi = 0; mi < 2; mi++)
                ldsm_x4(a[mi][0], a[mi][1], a[mi][2], a[mi][3],
                        sm0 + ((wm + mi * 16 + x4r) * 132 + kwg + x4c) * 4);
            #pragma unroll
            for (int np = 0; np < 4; np++) {
                uint32_t b0, b1, b2, b3;
                ldsm_x4(b0, b1, b2, b3,
                        Bb + ((wn + np * 16 + bx4r) * 20 + kw + bx4c) * 4);
                mma_bf16(c[0][2*np],   a[0][0], a[0][1], a[0][2], a[0][3], b0, b1);
                mma_bf16(c[1][2*np],   a[1][0], a[1][1], a[1][2], a[1][3], b0, b1);
                mma_bf16(c[0][2*np+1], a[0][0], a[0][1], a[0][2], a[0][3], b2, b3);
                mma_bf16(c[1][2*np+1], a[1][0], a[1][1], a[1][2], a[1][3], b2, b3);
            }
        }
    };
    auto zeroC = [&]() {
        #pragma unroll
        for (int mi = 0; mi < 2; mi++)
            #pragma unroll
            for (int ni = 0; ni < 8; ni++)
                #pragma unroll
                for (int r = 0; r < 4; r++) c[mi][ni][r] = 0.f;
    };
    auto run_phase = [&](const bf16* W) {
        zeroC();
        loadW(0, 0, W); CP_COMMIT();
        loadW(1, 32, W); CP_COMMIT();
        CP_WAIT1();
        __syncthreads();
        for (int it = 0; it < 8; ++it) {
            if (it + 2 < 8) loadW((it + 2) % 3, (it + 2) * 32, W);
            CP_COMMIT();
            compS(it % 3, it);
            CP_WAIT1();
            __syncthreads();
        }
    };

    // ---- phase 1: proj (A = attn out in tileA) ----
    run_phase(Wp);
    {
        float s0[2] = {0.f, 0.f}, q0[2] = {0.f, 0.f};
        float s1[2] = {0.f, 0.f}, q1[2] = {0.f, 0.f};
        #pragma unroll
        for (int mi = 0; mi < 2; mi++) {
            #pragma unroll
            for (int ni = 0; ni < 8; ni++) {
                int col = wn + ni * 8 + 2 * t;
                float b0 = pbias[col], b1 = pbias[col + 1];
                float2 ra = *(const float2*)(x + t0[mi] * 256 + col);
                float2 rb = *(const float2*)(x + t1[mi] * 256 + col);
                float v0 = c[mi][ni][0] + b0 + ra.x;
                float v1 = c[mi][ni][1] + b1 + ra.y;
                float v2 = c[mi][ni][2] + b0 + rb.x;
                float v3 = c[mi][ni][3] + b1 + rb.y;
                *(float2*)(out + t0[mi] * 256 + col) = make_float2(v0, v1);
                *(float2*)(out + t1[mi] * 256 + col) = make_float2(v2, v3);
                c[mi][ni][0] = v0; c[mi][ni][1] = v1;
                c[mi][ni][2] = v2; c[mi][ni][3] = v3;
                s0[mi] += v0 + v1; q0[mi] += v0 * v0 + v1 * v1;
                s1[mi] += v2 + v3; q1[mi] += v2 * v2 + v3 * v3;
            }
        }
        #pragma unroll
        for (int o = 1; o < 4; o <<= 1) {
            #pragma unroll
            for (int mi = 0; mi < 2; mi++) {
                s0[mi] += __shfl_xor_sync(0xffffffffu, s0[mi], o);
                q0[mi] += __shfl_xor_sync(0xffffffffu, q0[mi], o);
                s1[mi] += __shfl_xor_sync(0xffffffffu, s1[mi], o);
                q1[mi] += __shfl_xor_sync(0xffffffffu, q1[mi], o);
            }
        }
        if (t == 0) {
            #pragma unroll
            for (int mi = 0; mi < 2; mi++) {
                red[lr0[mi] * 8 + wnid * 2]     = s0[mi];
                red[lr0[mi] * 8 + wnid * 2 + 1] = q0[mi];
                red[lr1[mi] * 8 + wnid * 2]     = s1[mi];
                red[lr1[mi] * 8 + wnid * 2 + 1] = q1[mi];
            }
        }
        __syncthreads();
        #pragma unroll
        for (int mi = 0; mi < 2; mi++) {
            float sa = 0.f, qa = 0.f, sb = 0.f, qb2 = 0.f;
            #pragma unroll
            for (int j = 0; j < 4; j++) {
                sa  += red[lr0[mi] * 8 + j * 2];
                qa  += red[lr0[mi] * 8 + j * 2 + 1];
                sb  += red[lr1[mi] * 8 + j * 2];
                qb2 += red[lr1[mi] * 8 + j * 2 + 1];
            }
            float m0 = sa * (1.0f / 256.0f);
            float i0 = rsqrtf(qa * (1.0f / 256.0f) - m0 * m0 + EPS_F);
            float m1 = sb * (1.0f / 256.0f);
            float i1 = rsqrtf(qb2 * (1.0f / 256.0f) - m1 * m1 + EPS_F);
            #pragma unroll
            for (int ni = 0; ni < 8; ni++) {
                int col = wn + ni * 8 + 2 * t;
                float2 gg = *(const float2*)(g2 + col);
                float2 bb = *(const float2*)(b2 + col);
                smW[lr0[mi] * 132 + (col >> 1)] =
                    pack_bf16((c[mi][ni][0] - m0) * i0 * gg.x + bb.x,
                              (c[mi][ni][1] - m0) * i0 * gg.y + bb.y);
                smW[lr1[mi] * 132 + (col >> 1)] =
                    pack_bf16((c[mi][ni][2] - m1) * i1 * gg.x + bb.x,
                              (c[mi][ni][3] - m1) * i1 * gg.y + bb.y);
            }
        }
    }
    __syncthreads();

    // ---- phase 2: fc1 + GELU ----
    run_phase(W1);
    #pragma unroll
    for (int mi = 0; mi < 2; mi++) {
        #pragma unroll
        for (int ni = 0; ni < 8; ni++) {
            int col = wn + ni * 8 + 2 * t;
            float b0 = fb1[col], b1 = fb1[col + 1];
            float v0 = c[mi][ni][0] + b0;
            float v1 = c[mi][ni][1] + b1;
            float v2 = c[mi][ni][2] + b0;
            float v3 = c[mi][ni][3] + b1;
            v0 = 0.5f * v0 * (1.0f + erff(v0 * 0.70710678118654752f));
            v1 = 0.5f * v1 * (1.0f + erff(v1 * 0.70710678118654752f));
            v2 = 0.5f * v2 * (1.0f + erff(v2 * 0.70710678118654752f));
            v3 = 0.5f * v3 * (1.0f + erff(v3 * 0.70710678118654752f));
            smW[lr0[mi] * 132 + (col >> 1)] = pack_bf16(v0, v1);
            smW[lr1[mi] * 132 + (col >> 1)] = pack_bf16(v2, v3);
        }
    }
    __syncthreads();

    // ---- phase 3: fc2 + residual (x2 re-read from out) ----
    run_phase(W2);
    #pragma unroll
    for (int mi = 0; mi < 2; mi++) {
        #pragma unroll
        for (int ni = 0; ni < 8; ni++) {
            int col = wn + ni * 8 + 2 * t;
            float b0 = fb2[col], b1 = fb2[col + 1];
            float2 ra = *(const float2*)(out + t0[mi] * 256 + col);
            float2 rb = *(const float2*)(out + t1[mi] * 256 + col);
            *(float2*)(out + t0[mi] * 256 + col) =
                make_float2(c[mi][ni][0] + b0 + ra.x, c[mi][ni][1] + b1 + ra.y);
            *(float2*)(out + t1[mi] * 256 + col) =
                make_float2(c[mi][ni][2] + b0 + rb.x, c[mi][ni][3] + b1 + rb.y);
        }
    }
}

// ================ merged weight convert (single launch) ================
__global__ void cvt_all(const float* __restrict__ qkv_w, const float* __restrict__ proj_w,
                        const float* __restrict__ fc1_w, const float* __restrict__ fc2_w,
                        bf16* __restrict__ wt)
{
    __shared__ float tsm[32][33];
    int bx = blockIdx.x;
    int k0 = blockIdx.y * 32;
    int tx = threadIdx.x, ty = threadIdx.y;
    if (bx < 24) {
        int n0 = bx * 32;
        int n = n0 + tx;
        int h = n / 96, j = n % 96;
        int cidx = (j >> 5) * 256 + h * 32 + (j & 31);
        tsm[ty][tx] = qkv_w[(size_t)(k0 + ty) * 768 + cidx];
        __syncthreads();
        wt[WT_QKV + (size_t)(n0 + ty) * 256 + k0 + tx] = __float2bfloat16_rn(tsm[tx][ty]);
    } else {
        int s = (bx - 24) >> 3;
        int n0 = ((bx - 24) & 7) * 32;
        const float* W = (s == 0) ? proj_w : ((s == 1) ? fc1_w : fc2_w);
        size_t base = (s == 0) ? WT_PROJ : ((s == 1) ? WT_FC1 : WT_FC2);
        tsm[ty][tx] = W[(size_t)(k0 + ty) * 256 + n0 + tx];
        __syncthreads();
        wt[base + (size_t)(n0 + ty) * 256 + k0 + tx] = __float2bfloat16_rn(tsm[tx][ty]);
    }
}

// ---------------- launch ----------------
extern "C" void kernel_launch(void* const* d_in, const int* in_sizes, int n_in,
                              void* d_out, int out_size)
{
    const float* x       = (const float*)d_in[0];
    const float* norm1_g = (const float*)d_in[1];
    const float* norm1_b = (const float*)d_in[2];
    const float* qkv_w   = (const float*)d_in[3];
    const float* qkv_b   = (const float*)d_in[4];
    const float* rel_b   = (const float*)d_in[5];
    const float* proj_w  = (const float*)d_in[6];
    const float* proj_b  = (const float*)d_in[7];
    const float* norm2_g = (const float*)d_in[8];
    const float* norm2_b = (const float*)d_in[9];
    const float* fc1_w   = (const float*)d_in[10];
    const float* fc1_b   = (const float*)d_in[11];
    const float* fc2_w   = (const float*)d_in[12];
    const float* fc2_b   = (const float*)d_in[13];
    float* out = (float*)d_out;

    bf16* p_wt;
    cudaGetSymbolAddress((void**)&p_wt, g_wt);

    cudaFuncSetAttribute(swin_block, cudaFuncAttributeMaxDynamicSharedMemorySize, M_SMEM);

    // 0) merged weight convert
    cvt_all<<<dim3(48, 8), dim3(32, 32)>>>(qkv_w, proj_w, fc1_w, fc2_w, p_wt);

    // 1) whole Swin block in one kernel: one window per CTA
    swin_block<<<NWIN, 256, M_SMEM>>>(
        x, norm1_g, norm1_b, p_wt + WT_QKV, qkv_b, rel_b,
        p_wt + WT_PROJ, proj_b, norm2_g, norm2_b,
        p_wt + WT_FC1, fc1_b, p_wt + WT_FC2, fc2_b, out);
}

// round 17
// speedup vs baseline: 1.2432x; 1.0088x over previous
#include <cuda_runtime.h>
#include <cuda_bf16.h>
#include <math.h>
#include <stdint.h>

// ---------------- problem constants ----------------
#define CC      256
#define NHEAD   8
#define HDIM    32
#define SSHIFT  4
#define NWIN    2048
#define TTOT    131072
#define SCALE_F 0.1767766952966369f
#define EPS_F   1e-5f

typedef __nv_bfloat16 bf16;
typedef __nv_bfloat162 bf162;

// ---------------- scratch ----------------
__device__ __align__(16) bf16 g_wt[768 * 256 + 3 * 256 * 256]; // bf16 weights

#define WT_QKV  0
#define WT_PROJ (768 * 256)
#define WT_FC1  (WT_PROJ + 256 * 256)
#define WT_FC2  (WT_FC1 + 256 * 256)

// ---------------- helpers ----------------
__device__ __forceinline__ uint32_t smem_u32(const void* p) {
    uint32_t a;
    asm("{ .reg .u64 t; cvta.to.shared.u64 t, %1; cvt.u32.u64 %0, t; }" : "=r"(a) : "l"(p));
    return a;
}
__device__ __forceinline__ void mma_bf16(float c[4],
                                         uint32_t a0, uint32_t a1, uint32_t a2, uint32_t a3,
                                         uint32_t b0, uint32_t b1) {
    asm volatile(
        "mma.sync.aligned.m16n8k16.row.col.f32.bf16.bf16.f32 "
        "{%0,%1,%2,%3}, {%4,%5,%6,%7}, {%8,%9}, {%0,%1,%2,%3};"
        : "+f"(c[0]), "+f"(c[1]), "+f"(c[2]), "+f"(c[3])
        : "r"(a0), "r"(a1), "r"(a2), "r"(a3), "r"(b0), "r"(b1));
}
__device__ __forceinline__ void ldsm_x4(uint32_t& r0, uint32_t& r1, uint32_t& r2, uint32_t& r3,
                                        uint32_t addr) {
    asm volatile("ldmatrix.sync.aligned.m8n8.x4.shared.b16 {%0,%1,%2,%3}, [%4];"
        : "=r"(r0), "=r"(r1), "=r"(r2), "=r"(r3) : "r"(addr));
}
__device__ __forceinline__ void ldsm_x2(uint32_t& r0, uint32_t& r1, uint32_t addr) {
    asm volatile("ldmatrix.sync.aligned.m8n8.x2.shared.b16 {%0,%1}, [%2];"
        : "=r"(r0), "=r"(r1) : "r"(addr));
}
__device__ __forceinline__ uint32_t pack_bf16(float x, float y) {
    bf162 v = __floats2bfloat162_rn(x, y);
    return *(uint32_t*)&v;
}
#define CP16(dst, src) \
    asm volatile("cp.async.cg.shared.global [%0], [%1], 16;" :: "r"(dst), "l"(src) : "memory")
#define CP_COMMIT() asm volatile("cp.async.commit_group;" ::: "memory")
#define CP_WAIT1()  asm volatile("cp.async.wait_group 1;" ::: "memory")
#define CP_WAIT0()  asm volatile("cp.async.wait_group 0;" ::: "memory")
#define BAR_ARRIVE(id, n) asm volatile("bar.arrive %0, %1;" :: "r"(id), "r"(n) : "memory")
#define BAR_SYNC(id, n)   asm volatile("bar.sync %0, %1;"   :: "r"(id), "r"(n) : "memory")

// windowed row -> original token row (reverse shift)
__device__ __forceinline__ long unwin_row(long wr) {
    int batch = (int)(wr >> 14);
    int win   = ((int)wr >> 6) & 255;
    int token = (int)wr & 63;
    int ys = ((win >> 4) << 3) + (token >> 3);
    int xs = ((win & 15) << 3) + (token & 7);
    int y  = (ys + SSHIFT) & 127;
    int xx = (xs + SSHIFT) & 127;
    return (long)batch * 16384 + y * 128 + xx;
}

// ================ smem layout (bytes) ================
#define M_TILEA 0
#define M_B     33792
#define M_QS    86016
#define M_KS    91136
#define M_VST   96256
#define M_PS    100864
#define M_LUT   110080
#define M_QB    111104
#define M_RED   111104
#define M_SMEM  114176

__global__ __launch_bounds__(256, 2)
void swin_block(const float* __restrict__ x,
                const float* __restrict__ g1, const float* __restrict__ b1v,
                const bf16* __restrict__ Wt3, const float* __restrict__ qkvb,
                const float* __restrict__ rel_bias,
                const bf16* __restrict__ Wp, const float* __restrict__ pbias,
                const float* __restrict__ g2, const float* __restrict__ b2,
                const bf16* __restrict__ W1, const float* __restrict__ fb1,
                const bf16* __restrict__ W2, const float* __restrict__ fb2,
                float* __restrict__ out)
{
    extern __shared__ char smc[];
    float*    smF = (float*)smc;
    uint32_t* smW = (uint32_t*)smc;
    bf16*     smH = (bf16*)smc;
    uint32_t  sm0 = smem_u32(smc);

    int tid = threadIdx.x, warp = tid >> 5, lane = tid & 31;
    int g = lane >> 2, t = lane & 3;
    int lr  = lane & 7;
    int x4r = lr + ((lane >> 3) & 1) * 8;
    int x4c = ((lane >> 4) & 1) * 4;
    int x2c = ((lane >> 3) & 1) * 4;
    int bx4r = lr + ((lane >> 4) & 1) * 8;
    int bx4c = ((lane >> 3) & 1) * 4;
    long bm = (long)blockIdx.x * 64;
    const int lrow = tid >> 2, lch = (tid & 3) * 8;

    float* qb  = smF + M_QB / 4;
    float* lut = smF + M_LUT / 4;

    #pragma unroll
    for (int i = 0; i < 3; i++) qb[tid + i * 256] = qkvb[tid + i * 256];

    auto loadB1 = [&](int buf, int h, int kc) {
        uint32_t Bs = sm0 + M_B + buf * 26112;
        const bf16* src = Wt3 + (size_t)h * 96 * 256 + kc * 128;
        #pragma unroll
        for (int i = 0; i < 6; i++) {
            int e = tid + i * 256;
            int row = e >> 4, c8 = (e & 15) * 8;
            CP16(Bs + row * 272 + c8 * 2, src + row * 256 + c8);
        }
    };
    auto loadW = [&](int buf, int k0, const bf16* W) {
        uint32_t Bs = sm0 + M_B + buf * 20480;
        #pragma unroll
        for (int i = 0; i < 4; i++) {
            int row = lrow + i * 64;
            CP16(Bs + row * 80 + lch * 2, W + (size_t)row * 256 + k0 + lch);
        }
    };

    loadB1(0, 0, 0); CP_COMMIT();
    loadB1(1, 0, 1); CP_COMMIT();

    // ---- LN1 + shifted-window gather into tileA ----
    for (int i = 0; i < 8; i++) {
        int r = warp * 8 + i;
        long srow = unwin_row(bm + r);
        const float4* px = (const float4*)(x + srow * 256);
        float4 v0 = px[lane * 2], v1 = px[lane * 2 + 1];
        float s  = v0.x + v0.y + v0.z + v0.w + v1.x + v1.y + v1.z + v1.w;
        float s2 = v0.x*v0.x + v0.y*v0.y + v0.z*v0.z + v0.w*v0.w
                 + v1.x*v1.x + v1.y*v1.y + v1.z*v1.z + v1.w*v1.w;
        #pragma unroll
        for (int o = 16; o > 0; o >>= 1) {
            s  += __shfl_xor_sync(0xffffffffu, s,  o);
            s2 += __shfl_xor_sync(0xffffffffu, s2, o);
        }
        float mean = s * (1.0f / 256.0f);
        float inv = rsqrtf(s2 * (1.0f / 256.0f) - mean * mean + EPS_F);
        float4 ga = *(const float4*)(g1 + lane * 8);
        float4 gb = *(const float4*)(g1 + lane * 8 + 4);
        float4 ba = *(const float4*)(b1v + lane * 8);
        float4 bb = *(const float4*)(b1v + lane * 8 + 4);
        uint4 o4;
        o4.x = pack_bf16((v0.x - mean) * inv * ga.x + ba.x, (v0.y - mean) * inv * ga.y + ba.y);
        o4.y = pack_bf16((v0.z - mean) * inv * ga.z + ba.z, (v0.w - mean) * inv * ga.w + ba.w);
        o4.z = pack_bf16((v1.x - mean) * inv * gb.x + bb.x, (v1.y - mean) * inv * gb.y + bb.y);
        o4.w = pack_bf16((v1.z - mean) * inv * gb.z + bb.z, (v1.w - mean) * inv * gb.w + bb.w);
        *(uint4*)(smH + r * 264 + lane * 8) = o4;
    }

    int wmq = (warp & 3) * 16;
    int wnq = (warp >> 2) * 48;

    uint32_t oacc[8][4];      // per-head PV output (packed bf16 pairs)

    #pragma unroll 1
    for (int h = 0; h < 8; h++) {
        CP_WAIT1();
        __syncthreads();

        // lut for head h: hoisted so its latency hides under the GEMM
        if (tid < 225) lut[tid] = rel_bias[tid * 8 + h];

        // ---- qkv GEMM for head h: 64x96x256 ----
        float c[6][4];
        #pragma unroll
        for (int ni = 0; ni < 6; ni++)
            #pragma unroll
            for (int r = 0; r < 4; r++) c[ni][r] = 0.f;

        #pragma unroll
        for (int kc = 0; kc < 2; kc++) {
            if (kc == 1) CP_WAIT0();
            uint32_t Bb = sm0 + M_B + kc * 26112;
            #pragma unroll
            for (int ks = 0; ks < 8; ks++) {
                int kw = ks * 8;
                uint32_t a0, a1, a2, a3;
                ldsm_x4(a0, a1, a2, a3,
                        sm0 + ((wmq + x4r) * 132 + kc * 64 + kw + x4c) * 4);
                #pragma unroll
                for (int ni = 0; ni < 6; ni++) {
                    uint32_t b0, b1;
                    ldsm_x2(b0, b1, Bb + ((wnq + ni * 8 + lr) * 68 + kw + x2c) * 4);
                    mma_bf16(c[ni], a0, a1, a2, a3, b0, b1);
                }
            }
        }

        // ---- stage q/k/v (+bias): branch-free per warp half ----
        {
            int lr0 = wmq + g, lr1 = lr0 + 8;
            if (warp < 4) {
                #pragma unroll
                for (int ni = 0; ni < 4; ni++) {
                    int cj = ni * 8 + 2 * t;
                    float bb0 = qb[h * 32 + cj], bb1 = qb[h * 32 + cj + 1];
                    smW[M_QS / 4 + lr0 * 20 + (cj >> 1)] = pack_bf16(c[ni][0] + bb0, c[ni][1] + bb1);
                    smW[M_QS / 4 + lr1 * 20 + (cj >> 1)] = pack_bf16(c[ni][2] + bb0, c[ni][3] + bb1);
                }
                #pragma unroll
                for (int ni = 4; ni < 6; ni++) {
                    int cj = (ni - 4) * 8 + 2 * t;
                    float bb0 = qb[256 + h * 32 + cj], bb1 = qb[256 + h * 32 + cj + 1];
                    smW[M_KS / 4 + lr0 * 20 + (cj >> 1)] = pack_bf16(c[ni][0] + bb0, c[ni][1] + bb1);
                    smW[M_KS / 4 + lr1 * 20 + (cj >> 1)] = pack_bf16(c[ni][2] + bb0, c[ni][3] + bb1);
                }
            } else {
                #pragma unroll
                for (int ni = 0; ni < 2; ni++) {
                    int cj = 16 + ni * 8 + 2 * t;
                    float bb0 = qb[256 + h * 32 + cj], bb1 = qb[256 + h * 32 + cj + 1];
                    smW[M_KS / 4 + lr0 * 20 + (cj >> 1)] = pack_bf16(c[ni][0] + bb0, c[ni][1] + bb1);
                    smW[M_KS / 4 + lr1 * 20 + (cj >> 1)] = pack_bf16(c[ni][2] + bb0, c[ni][3] + bb1);
                }
                bf16* ve = smH + M_VST / 2;
                #pragma unroll
                for (int ni = 2; ni < 6; ni++) {
                    int cj = (ni - 2) * 8 + 2 * t;
                    float bb0 = qb[512 + h * 32 + cj], bb1 = qb[512 + h * 32 + cj + 1];
                    ve[cj * 72 + lr0]       = __float2bfloat16_rn(c[ni][0] + bb0);
                    ve[(cj + 1) * 72 + lr0] = __float2bfloat16_rn(c[ni][1] + bb1);
                    ve[cj * 72 + lr1]       = __float2bfloat16_rn(c[ni][2] + bb0);
                    ve[(cj + 1) * 72 + lr1] = __float2bfloat16_rn(c[ni][3] + bb1);
                }
            }
        }
        __syncthreads();

        if (h < 7) {
            loadB1(0, h + 1, 0); CP_COMMIT();
            loadB1(1, h + 1, 1); CP_COMMIT();
        }

        // ---- QK + softmax (no max subtraction): warps 0..3 produce P rows
        //      16w..16w+15 == exactly the rows their own PV tile reads.
        if (warp < 4) {
            int wm2 = warp * 16;
            float s[8][4];
            #pragma unroll
            for (int ni = 0; ni < 8; ni++)
                #pragma unroll
                for (int r = 0; r < 4; r++) s[ni][r] = 0.f;

            #pragma unroll
            for (int kt = 0; kt < 2; kt++) {
                int kw = kt * 8;
                uint32_t a0, a1, a2, a3;
                ldsm_x4(a0, a1, a2, a3,
                        sm0 + M_QS + ((wm2 + x4r) * 20 + kw + x4c) * 4);
                #pragma unroll
                for (int ni = 0; ni < 8; ni++) {
                    uint32_t b0, b1;
                    ldsm_x2(b0, b1, sm0 + M_KS + ((ni * 8 + lr) * 20 + kw + x2c) * 4);
                    mma_bf16(s[ni], a0, a1, a2, a3, b0, b1);
                }
            }

            int r0 = wm2 + g, r1 = wm2 + g + 8;
            int rh0 = r0 >> 3, rw0 = r0 & 7;
            int rh1 = r1 >> 3, rw1 = r1 & 7;
            float sum0 = 0.f, sum1 = 0.f;
            #pragma unroll
            for (int ni = 0; ni < 8; ni++) {
                #pragma unroll
                for (int cc2 = 0; cc2 < 2; cc2++) {
                    int col = ni * 8 + 2 * t + cc2;
                    int mh = col >> 3, mw = col & 7;
                    s[ni][cc2]     = __expf(s[ni][cc2]     * SCALE_F + lut[(rh0 - mh + 7) * 15 + (rw0 - mw + 7)]);
                    s[ni][2 + cc2] = __expf(s[ni][2 + cc2] * SCALE_F + lut[(rh1 - mh + 7) * 15 + (rw1 - mw + 7)]);
                    sum0 += s[ni][cc2];
                    sum1 += s[ni][2 + cc2];
                }
            }
            sum0 += __shfl_xor_sync(0xffffffffu, sum0, 1);
            sum0 += __shfl_xor_sync(0xffffffffu, sum0, 2);
            sum1 += __shfl_xor_sync(0xffffffffu, sum1, 1);
            sum1 += __shfl_xor_sync(0xffffffffu, sum1, 2);
            float inv0 = 1.0f / sum0, inv1 = 1.0f / sum1;
            #pragma unroll
            for (int ni = 0; ni < 8; ni++) {
                smW[M_PS / 4 + r0 * 36 + ni * 4 + t] = pack_bf16(s[ni][0] * inv0, s[ni][1] * inv0);
                smW[M_PS / 4 + r1 * 36 + ni * 4 + t] = pack_bf16(s[ni][2] * inv1, s[ni][3] * inv1);
            }
            BAR_ARRIVE(1, 256);      // release P to warps 4..7; don't block
            __syncwarp();            // cross-lane visibility for own ldsm
        } else {
            BAR_SYNC(1, 256);        // wait for warps 0..3's P
        }

        // ---- PV: all 8 warps, 16 rows x 16 cols -> oacc ----
        {
            int rowb = (warp & 3) * 16, colb = (warp >> 2) * 16;
            float o[2][4];
            #pragma unroll
            for (int ni = 0; ni < 2; ni++)
                #pragma unroll
                for (int r = 0; r < 4; r++) o[ni][r] = 0.f;
            #pragma unroll
            for (int kt = 0; kt < 4; kt++) {
                int kw = kt * 8;
                uint32_t a0, a1, a2, a3;
                ldsm_x4(a0, a1, a2, a3,
                        sm0 + M_PS + ((rowb + x4r) * 36 + kw + x4c) * 4);
                #pragma unroll
                for (int ni = 0; ni < 2; ni++) {
                    uint32_t b0, b1;
                    ldsm_x2(b0, b1, sm0 + M_VST + ((colb + ni * 8 + lr) * 36 + kw + x2c) * 4);
                    mma_bf16(o[ni], a0, a1, a2, a3, b0, b1);
                }
            }
            #pragma unroll
            for (int ni = 0; ni < 2; ni++) {
                oacc[h][ni * 2]     = pack_bf16(o[ni][0], o[ni][1]);
                oacc[h][ni * 2 + 1] = pack_bf16(o[ni][2], o[ni][3]);
            }
        }
    }

    // ---- dump attn out into tileA (tileA reads are barriers old; PV peers
    //      touch only PS/VST) ----
    {
        int rowb = (warp & 3) * 16, colb = (warp >> 2) * 16;
        #pragma unroll
        for (int h = 0; h < 8; h++) {
            #pragma unroll
            for (int ni = 0; ni < 2; ni++) {
                int wcol = h * 16 + (colb >> 1) + ni * 4 + t;
                smW[(rowb + g) * 132 + wcol]     = oacc[h][ni * 2];
                smW[(rowb + g + 8) * 132 + wcol] = oacc[h][ni * 2 + 1];
            }
        }
    }
    __syncthreads();

    // ================== block2 phases ==================
    int wm = (warp & 1) * 32, wn = (warp >> 1) * 64, wnid = warp >> 1;
    float* red = smF + M_RED / 4;

    int lr0[2], lr1[2];
    long t0[2], t1[2];
    #pragma unroll
    for (int mi = 0; mi < 2; mi++) {
        lr0[mi] = wm + mi * 16 + g;
        lr1[mi] = lr0[mi] + 8;
        t0[mi] = unwin_row(bm + lr0[mi]);
        t1[mi] = unwin_row(bm + lr1[mi]);
    }

    float c[2][8][4];

    auto compS = [&](int buf, int itk) {
        uint32_t Bb = sm0 + M_B + buf * 20480;
        #pragma unroll
        for (int kt = 0; kt < 2; kt++) {
            int kwg = itk * 16 + kt * 8;
            int kw = kt * 8;
            uint32_t a[2][4];
            #pragma unroll
            for (int mi = 0; mi < 2; mi++)
                ldsm_x4(a[mi][0], a[mi][1], a[mi][2], a[mi][3],
                        sm0 + ((wm + mi * 16 + x4r) * 132 + kwg + x4c) * 4);
            #pragma unroll
            for (int np = 0; np < 4; np++) {
                uint32_t b0, b1, b2, b3;
                ldsm_x4(b0, b1, b2, b3,
                        Bb + ((wn + np * 16 + bx4r) * 20 + kw + bx4c) * 4);
                mma_bf16(c[0][2*np],   a[0][0], a[0][1], a[0][2], a[0][3], b0, b1);
                mma_bf16(c[1][2*np],   a[1][0], a[1][1], a[1][2], a[1][3], b0, b1);
                mma_bf16(c[0][2*np+1], a[0][0], a[0][1], a[0][2], a[0][3], b2, b3);
                mma_bf16(c[1][2*np+1], a[1][0], a[1][1], a[1][2], a[1][3], b2, b3);
            }
        }
    };
    auto zeroC = [&]() {
        #pragma unroll
        for (int mi = 0; mi < 2; mi++)
            #pragma unroll
            for (int ni = 0; ni < 8; ni++)
                #pragma unroll
                for (int r = 0; r < 4; r++) c[mi][ni][r] = 0.f;
    };
    auto run_phase = [&](const bf16* W) {
        zeroC();
        loadW(0, 0, W); CP_COMMIT();
        loadW(1, 32, W); CP_COMMIT();
        CP_WAIT1();
        __syncthreads();
        for (int it = 0; it < 8; ++it) {
            if (it + 2 < 8) loadW((it + 2) % 3, (it + 2) * 32, W);
            CP_COMMIT();
            compS(it % 3, it);
            CP_WAIT1();
            __syncthreads();
        }
    };

    // ---- phase 1: proj (A = attn out in tileA) ----
    run_phase(Wp);
    {
        float s0[2] = {0.f, 0.f}, q0[2] = {0.f, 0.f};
        float s1[2] = {0.f, 0.f}, q1[2] = {0.f, 0.f};
        #pragma unroll
        for (int mi = 0; mi < 2; mi++) {
            #pragma unroll
            for (int ni = 0; ni < 8; ni++) {
                int col = wn + ni * 8 + 2 * t;
                float b0 = pbias[col], b1 = pbias[col + 1];
                float2 ra = *(const float2*)(x + t0[mi] * 256 + col);
                float2 rb = *(const float2*)(x + t1[mi] * 256 + col);
                float v0 = c[mi][ni][0] + b0 + ra.x;
                float v1 = c[mi][ni][1] + b1 + ra.y;
                float v2 = c[mi][ni][2] + b0 + rb.x;
                float v3 = c[mi][ni][3] + b1 + rb.y;
                *(float2*)(out + t0[mi] * 256 + col) = make_float2(v0, v1);
                *(float2*)(out + t1[mi] * 256 + col) = make_float2(v2, v3);
                c[mi][ni][0] = v0; c[mi][ni][1] = v1;
                c[mi][ni][2] = v2; c[mi][ni][3] = v3;
                s0[mi] += v0 + v1; q0[mi] += v0 * v0 + v1 * v1;
                s1[mi] += v2 + v3; q1[mi] += v2 * v2 + v3 * v3;
            }
        }
        #pragma unroll
        for (int o = 1; o < 4; o <<= 1) {
            #pragma unroll
            for (int mi = 0; mi < 2; mi++) {
                s0[mi] += __shfl_xor_sync(0xffffffffu, s0[mi], o);
                q0[mi] += __shfl_xor_sync(0xffffffffu, q0[mi], o);
                s1[mi] += __shfl_xor_sync(0xffffffffu, s1[mi], o);
                q1[mi] += __shfl_xor_sync(0xffffffffu, q1[mi], o);
            }
        }
        if (t == 0) {
            #pragma unroll
            for (int mi = 0; mi < 2; mi++) {
                red[lr0[mi] * 8 + wnid * 2]     = s0[mi];
                red[lr0[mi] * 8 + wnid * 2 + 1] = q0[mi];
                red[lr1[mi] * 8 + wnid * 2]     = s1[mi];
                red[lr1[mi] * 8 + wnid * 2 + 1] = q1[mi];
            }
        }
        __syncthreads();
        #pragma unroll
        for (int mi = 0; mi < 2; mi++) {
            float sa = 0.f, qa = 0.f, sb = 0.f, qb2 = 0.f;
            #pragma unroll
            for (int j = 0; j < 4; j++) {
                sa  += red[lr0[mi] * 8 + j * 2];
                qa  += red[lr0[mi] * 8 + j * 2 + 1];
                sb  += red[lr1[mi] * 8 + j * 2];
                qb2 += red[lr1[mi] * 8 + j * 2 + 1];
            }
            float m0 = sa * (1.0f / 256.0f);
            float i0 = rsqrtf(qa * (1.0f / 256.0f) - m0 * m0 + EPS_F);
            float m1 = sb * (1.0f / 256.0f);
            float i1 = rsqrtf(qb2 * (1.0f / 256.0f) - m1 * m1 + EPS_F);
            #pragma unroll
            for (int ni = 0; ni < 8; ni++) {
                int col = wn + ni * 8 + 2 * t;
                float2 gg = *(const float2*)(g2 + col);
                float2 bb = *(const float2*)(b2 + col);
                smW[lr0[mi] * 132 + (col >> 1)] =
                    pack_bf16((c[mi][ni][0] - m0) * i0 * gg.x + bb.x,
                              (c[mi][ni][1] - m0) * i0 * gg.y + bb.y);
                smW[lr1[mi] * 132 + (col >> 1)] =
                    pack_bf16((c[mi][ni][2] - m1) * i1 * gg.x + bb.x,
                              (c[mi][ni][3] - m1) * i1 * gg.y + bb.y);
            }
        }
    }
    __syncthreads();

    // ---- phase 2: fc1 + GELU ----
    run_phase(W1);
    #pragma unroll
    for (int mi = 0; mi < 2; mi++) {
        #pragma unroll
        for (int ni = 0; ni < 8; ni++) {
            int col = wn + ni * 8 + 2 * t;
            float b0 = fb1[col], b1 = fb1[col + 1];
            float v0 = c[mi][ni][0] + b0;
            float v1 = c[mi][ni][1] + b1;
            float v2 = c[mi][ni][2] + b0;
            float v3 = c[mi][ni][3] + b1;
            v0 = 0.5f * v0 * (1.0f + erff(v0 * 0.70710678118654752f));
            v1 = 0.5f * v1 * (1.0f + erff(v1 * 0.70710678118654752f));
            v2 = 0.5f * v2 * (1.0f + erff(v2 * 0.70710678118654752f));
            v3 = 0.5f * v3 * (1.0f + erff(v3 * 0.70710678118654752f));
            smW[lr0[mi] * 132 + (col >> 1)] = pack_bf16(v0, v1);
            smW[lr1[mi] * 132 + (col >> 1)] = pack_bf16(v2, v3);
        }
    }
    __syncthreads();

    // ---- phase 3: fc2 + residual (x2 re-read from out) ----
    run_phase(W2);
    #pragma unroll
    for (int mi = 0; mi < 2; mi++) {
        #pragma unroll
        for (int ni = 0; ni < 8; ni++) {
            int col = wn + ni * 8 + 2 * t;
            float b0 = fb2[col], b1 = fb2[col + 1];
            float2 ra = *(const float2*)(out + t0[mi] * 256 + col);
            float2 rb = *(const float2*)(out + t1[mi] * 256 + col);
            *(float2*)(out + t0[mi] * 256 + col) =
                make_float2(c[mi][ni][0] + b0 + ra.x, c[mi][ni][1] + b1 + ra.y);
            *(float2*)(out + t1[mi] * 256 + col) =
                make_float2(c[mi][ni][2] + b0 + rb.x, c[mi][ni][3] + b1 + rb.y);
        }
    }
}

// ================ merged weight convert (single launch) ================
__global__ void cvt_all(const float* __restrict__ qkv_w, const float* __restrict__ proj_w,
                        const float* __restrict__ fc1_w, const float* __restrict__ fc2_w,
                        bf16* __restrict__ wt)
{
    __shared__ float tsm[32][33];
    int bx = blockIdx.x;
    int k0 = blockIdx.y * 32;
    int tx = threadIdx.x, ty = threadIdx.y;
    if (bx < 24) {
        int n0 = bx * 32;
        int n = n0 + tx;
        int h = n / 96, j = n % 96;
        int cidx = (j >> 5) * 256 + h * 32 + (j & 31);
        tsm[ty][tx] = qkv_w[(size_t)(k0 + ty) * 768 + cidx];
        __syncthreads();
        wt[WT_QKV + (size_t)(n0 + ty) * 256 + k0 + tx] = __float2bfloat16_rn(tsm[tx][ty]);
    } else {
        int s = (bx - 24) >> 3;
        int n0 = ((bx - 24) & 7) * 32;
        const float* W = (s == 0) ? proj_w : ((s == 1) ? fc1_w : fc2_w);
        size_t base = (s == 0) ? WT_PROJ : ((s == 1) ? WT_FC1 : WT_FC2);
        tsm[ty][tx] = W[(size_t)(k0 + ty) * 256 + n0 + tx];
        __syncthreads();
        wt[base + (size_t)(n0 + ty) * 256 + k0 + tx] = __float2bfloat16_rn(tsm[tx][ty]);
    }
}

// ---------------- launch ----------------
extern "C" void kernel_launch(void* const* d_in, const int* in_sizes, int n_in,
                              void* d_out, int out_size)
{
    const float* x       = (const float*)d_in[0];
    const float* norm1_g = (const float*)d_in[1];
    const float* norm1_b = (const float*)d_in[2];
    const float* qkv_w   = (const float*)d_in[3];
    const float* qkv_b   = (const float*)d_in[4];
    const float* rel_b   = (const float*)d_in[5];
    const float* proj_w  = (const float*)d_in[6];
    const float* proj_b  = (const float*)d_in[7];
    const float* norm2_g = (const float*)d_in[8];
    const float* norm2_b = (const float*)d_in[9];
    const float* fc1_w   = (const float*)d_in[10];
    const float* fc1_b   = (const float*)d_in[11];
    const float* fc2_w   = (const float*)d_in[12];
    const float* fc2_b   = (const float*)d_in[13];
    float* out = (float*)d_out;

    bf16* p_wt;
    cudaGetSymbolAddress((void**)&p_wt, g_wt);

    cudaFuncSetAttribute(swin_block, cudaFuncAttributeMaxDynamicSharedMemorySize, M_SMEM);

    // 0) merged weight convert
    cvt_all<<<dim3(48, 8), dim3(32, 32)>>>(qkv_w, proj_w, fc1_w, fc2_w, p_wt);

    // 1) whole Swin block in one kernel: one window per CTA
    swin_block<<<NWIN, 256, M_SMEM>>>(
        x, norm1_g, norm1_b, p_wt + WT_QKV, qkv_b, rel_b,
        p_wt + WT_PROJ, proj_b, norm2_g, norm2_b,
        p_wt + WT_FC1, fc1_b, p_wt + WT_FC2, fc2_b, out);
}